// round 1
// baseline (speedup 1.0000x reference)
#include <cuda_runtime.h>
#include <math.h>

#define Bb 4
#define Nn 2048
#define Dd 2048

// ---- scratch (static __device__; no allocations allowed) ----
__device__ float g_cn[(size_t)Bb * Nn * Dd];       // 64 MB
__device__ float g_sim[(size_t)Bb * Nn * Nn];      // 64 MB
__device__ float g_pe[(size_t)Nn * Dd];            // 16 MB
__device__ float g_v[(size_t)Bb * Nn * Nn];        // 64 MB
__device__ float g_csum[Bb * Nn];
__device__ float g_counter[(size_t)Bb * Nn * Dd];  // 64 MB

// ---- GEMM tiling ----
#define BM 128
#define BN 128
#define BK 16
#define TM 8
#define TN 8
#define NT 256

// A: [*,K] row-major, lda between rows; points at block's first row (m0 applied).
// TRANSB=true : Bp is [*,K] row-major (n0 row offset applied), like A.
// TRANSB=false: Bp is [K,*] row-major (n0 column offset applied).
template <bool TRANSB>
__device__ __forceinline__ void gemm_mainloop(
    const float* __restrict__ A, int lda,
    const float* __restrict__ Bp, int ldb,
    int K,
    float (*As)[BM], float (*Bs)[BN],
    float acc[TM][TN])
{
    const int tid = threadIdx.x;
    const int tx  = tid & 15;
    const int ty  = tid >> 4;
    const int ar  = tid >> 2;          // 0..63
    const int ak  = (tid & 3) << 2;    // 0,4,8,12
    const int bkr = tid >> 5;          // 0..7
    const int bnc = (tid & 31) << 2;   // 0..124

    for (int k0 = 0; k0 < K; k0 += BK) {
        // load A tile (BM x BK), store transposed into As[k][m]
        #pragma unroll
        for (int it = 0; it < 2; ++it) {
            int row = ar + it * 64;
            float4 v = *(const float4*)(A + (size_t)row * lda + k0 + ak);
            As[ak + 0][row] = v.x; As[ak + 1][row] = v.y;
            As[ak + 2][row] = v.z; As[ak + 3][row] = v.w;
        }
        if (TRANSB) {
            #pragma unroll
            for (int it = 0; it < 2; ++it) {
                int row = ar + it * 64;
                float4 v = *(const float4*)(Bp + (size_t)row * ldb + k0 + ak);
                Bs[ak + 0][row] = v.x; Bs[ak + 1][row] = v.y;
                Bs[ak + 2][row] = v.z; Bs[ak + 3][row] = v.w;
            }
        } else {
            #pragma unroll
            for (int it = 0; it < 2; ++it) {
                int k = bkr + it * 8;
                float4 v = *(const float4*)(Bp + (size_t)(k0 + k) * ldb + bnc);
                *(float4*)(&Bs[k][bnc]) = v;
            }
        }
        __syncthreads();
        #pragma unroll
        for (int kk = 0; kk < BK; ++kk) {
            float a[TM], b[TN];
            *(float4*)&a[0] = *(const float4*)&As[kk][ty * TM];
            *(float4*)&a[4] = *(const float4*)&As[kk][ty * TM + 4];
            *(float4*)&b[0] = *(const float4*)&Bs[kk][tx * TN];
            *(float4*)&b[4] = *(const float4*)&Bs[kk][tx * TN + 4];
            #pragma unroll
            for (int i = 0; i < TM; ++i)
                #pragma unroll
                for (int j = 0; j < TN; ++j)
                    acc[i][j] = fmaf(a[i], b[j], acc[i][j]);
        }
        __syncthreads();
    }
}

// ---- pointwise kernels ----

__global__ __launch_bounds__(256) void k_normalize(const float* __restrict__ data)
{
    const int row = blockIdx.x;                 // b*Nn + n
    const float* in = data + (size_t)row * Dd;
    float* out = g_cn + (size_t)row * Dd;
    float s = 0.f;
    for (int i = threadIdx.x; i < Dd; i += 256) { float v = in[i]; s += v * v; }
    __shared__ float red[32];
    #pragma unroll
    for (int o = 16; o; o >>= 1) s += __shfl_down_sync(0xffffffffu, s, o);
    if ((threadIdx.x & 31) == 0) red[threadIdx.x >> 5] = s;
    __syncthreads();
    if (threadIdx.x < 32) {
        float v = (threadIdx.x < 8) ? red[threadIdx.x] : 0.f;
        #pragma unroll
        for (int o = 4; o; o >>= 1) v += __shfl_down_sync(0xffffffffu, v, o);
        if (threadIdx.x == 0) red[0] = rsqrtf(fmaxf(v, 1e-12f));
    }
    __syncthreads();
    const float r = red[0];
    for (int i = threadIdx.x; i < Dd; i += 256) out[i] = in[i] * r;
}

__global__ __launch_bounds__(256) void k_posenc()
{
    const int idx = blockIdx.x * 256 + threadIdx.x;  // over Nn*Dd
    const int n = idx / Dd;
    const int i = idx - n * Dd;
    const float e = (float)(2 * (i / 2)) / (float)Dd;
    const float rate = 1.0f / powf(10000.0f, e);
    const float ang = (float)n * rate;
    g_pe[idx] = (i & 1) ? cosf(ang) : sinf(ang);
}

__global__ __launch_bounds__(256) void k_rowsum()
{
    const int row = blockIdx.x;                 // b*Nn + n
    const float* s = g_sim + (size_t)row * Nn;
    float acc = 0.f;
    for (int i = threadIdx.x; i < Nn; i += 256) acc += s[i];
    __shared__ float red[32];
    #pragma unroll
    for (int o = 16; o; o >>= 1) acc += __shfl_down_sync(0xffffffffu, acc, o);
    if ((threadIdx.x & 31) == 0) red[threadIdx.x >> 5] = acc;
    __syncthreads();
    if (threadIdx.x < 32) {
        float v = (threadIdx.x < 8) ? red[threadIdx.x] : 0.f;
        #pragma unroll
        for (int o = 4; o; o >>= 1) v += __shfl_down_sync(0xffffffffu, v, o);
        if (threadIdx.x == 0) g_csum[row] = v;
    }
}

// ---- GEMM kernels ----

// sim = relu(cn @ cn^T)     [per batch, NT-gemm]
__global__ __launch_bounds__(NT) void k_gemm_sim()
{
    __shared__ float As[BK][BM];
    __shared__ float Bs[BK][BN];
    const int b = blockIdx.z;
    const int m0 = blockIdx.y * BM;
    const int n0 = blockIdx.x * BN;
    const float* Abase = g_cn + ((size_t)b * Nn + m0) * Dd;
    const float* Bbase = g_cn + ((size_t)b * Nn + n0) * Dd;
    float acc[TM][TN] = {};
    gemm_mainloop<true>(Abase, Dd, Bbase, Dd, Dd, As, Bs, acc);
    const int tx = threadIdx.x & 15, ty = threadIdx.x >> 4;
    float* C = g_sim + (size_t)b * Nn * Nn;
    #pragma unroll
    for (int i = 0; i < TM; ++i) {
        const int row = m0 + ty * TM + i;
        #pragma unroll
        for (int j = 0; j < TN; j += 4) {
            float4 v;
            v.x = fmaxf(acc[i][j + 0], 0.f);
            v.y = fmaxf(acc[i][j + 1], 0.f);
            v.z = fmaxf(acc[i][j + 2], 0.f);
            v.w = fmaxf(acc[i][j + 3], 0.f);
            *(float4*)(C + (size_t)row * Nn + n0 + tx * TN + j) = v;
        }
    }
}

// v = posenc @ sim[b]       [NN-gemm]
__global__ __launch_bounds__(NT) void k_gemm_v()
{
    __shared__ float As[BK][BM];
    __shared__ float Bs[BK][BN];
    const int b = blockIdx.z;
    const int m0 = blockIdx.y * BM;
    const int n0 = blockIdx.x * BN;
    const float* Abase = g_pe + (size_t)m0 * Nn;
    const float* Bbase = g_sim + (size_t)b * Nn * Nn + n0;
    float acc[TM][TN] = {};
    gemm_mainloop<false>(Abase, Nn, Bbase, Nn, Nn, As, Bs, acc);
    const int tx = threadIdx.x & 15, ty = threadIdx.x >> 4;
    float* C = g_v + (size_t)b * Nn * Nn;
    #pragma unroll
    for (int i = 0; i < TM; ++i) {
        const int row = m0 + ty * TM + i;
        #pragma unroll
        for (int j = 0; j < TN; j += 4) {
            *(float4*)(C + (size_t)row * Nn + n0 + tx * TN + j) = *(float4*)&acc[i][j];
        }
    }
}

// counter = softplus(v @ W_exp[1:] + csum*W_exp[0] + b_exp)
__global__ __launch_bounds__(NT) void k_gemm_counter(const float* __restrict__ W_exp,
                                                     const float* __restrict__ b_exp)
{
    __shared__ float As[BK][BM];
    __shared__ float Bs[BK][BN];
    const int b = blockIdx.z;
    const int m0 = blockIdx.y * BM;
    const int n0 = blockIdx.x * BN;
    const float* Abase = g_v + (size_t)b * Nn * Nn + (size_t)m0 * Nn;
    const float* Bbase = W_exp + Dd + n0;   // row 1 of W_exp, column offset n0
    float acc[TM][TN] = {};
    gemm_mainloop<false>(Abase, Nn, Bbase, Dd, Nn, As, Bs, acc);
    const int tx = threadIdx.x & 15, ty = threadIdx.x >> 4;
    float w0[TN], be[TN];
    #pragma unroll
    for (int j = 0; j < TN; ++j) {
        w0[j] = W_exp[n0 + tx * TN + j];    // row 0
        be[j] = b_exp[n0 + tx * TN + j];
    }
    float* C = g_counter + (size_t)b * Nn * Dd;
    #pragma unroll
    for (int i = 0; i < TM; ++i) {
        const int row = m0 + ty * TM + i;
        const float cs = g_csum[b * Nn + row];
        #pragma unroll
        for (int j = 0; j < TN; j += 4) {
            float4 v;
            #pragma unroll
            for (int q = 0; q < 4; ++q) {
                float x = acc[i][j + q] + cs * w0[j + q] + be[j + q];
                // softplus, overflow-safe: max(x,0) + log1p(exp(-|x|))
                ((float*)&v)[q] = fmaxf(x, 0.f) + log1pf(expf(-fabsf(x)));
            }
            *(float4*)(C + (size_t)row * Dd + n0 + tx * TN + j) = v;
        }
    }
}

// out = data @ W_merge[:D] + counter @ W_merge[D:]
__global__ __launch_bounds__(NT) void k_gemm_out(const float* __restrict__ data,
                                                 const float* __restrict__ W_merge,
                                                 float* __restrict__ out)
{
    __shared__ float As[BK][BM];
    __shared__ float Bs[BK][BN];
    const int b = blockIdx.z;
    const int m0 = blockIdx.y * BM;
    const int n0 = blockIdx.x * BN;
    float acc[TM][TN] = {};
    // K-half 1: data with top half of W_merge
    gemm_mainloop<false>(data + ((size_t)b * Nn + m0) * Dd, Dd,
                         W_merge + n0, Dd, Dd, As, Bs, acc);
    // K-half 2: counter with bottom half of W_merge
    gemm_mainloop<false>(g_counter + ((size_t)b * Nn + m0) * Dd, Dd,
                         W_merge + (size_t)Dd * Dd + n0, Dd, Dd, As, Bs, acc);
    const int tx = threadIdx.x & 15, ty = threadIdx.x >> 4;
    float* C = out + (size_t)b * Nn * Dd;
    #pragma unroll
    for (int i = 0; i < TM; ++i) {
        const int row = m0 + ty * TM + i;
        #pragma unroll
        for (int j = 0; j < TN; j += 4) {
            *(float4*)(C + (size_t)row * Dd + n0 + tx * TN + j) = *(float4*)&acc[i][j];
        }
    }
}

extern "C" void kernel_launch(void* const* d_in, const int* in_sizes, int n_in,
                              void* d_out, int out_size)
{
    const float* data    = (const float*)d_in[0];
    const float* W_exp   = (const float*)d_in[1];
    const float* b_exp   = (const float*)d_in[2];
    const float* W_merge = (const float*)d_in[3];
    float* out = (float*)d_out;
    (void)in_sizes; (void)n_in; (void)out_size;

    const dim3 gemm_grid(Nn / BN, Nn / BM, Bb);

    k_normalize<<<Bb * Nn, 256>>>(data);
    k_posenc<<<(Nn * Dd) / 256, 256>>>();
    k_gemm_sim<<<gemm_grid, NT>>>();
    k_rowsum<<<Bb * Nn, 256>>>();
    k_gemm_v<<<gemm_grid, NT>>>();
    k_gemm_counter<<<gemm_grid, NT>>>(W_exp, b_exp);
    k_gemm_out<<<gemm_grid, NT>>>(data, W_merge, out);
}

// round 4
// speedup vs baseline: 3.6853x; 3.6853x over previous
#include <cuda_runtime.h>
#include <cuda_bf16.h>
#include <math.h>
#include <stdint.h>

#define Bb 4
#define Nn 2048
#define Dd 2048
typedef __nv_bfloat16 bf16;

// ---- scratch (static __device__; no allocations allowed) ----
__device__ bf16 g_cn_hi[(size_t)Bb * Nn * Dd];
__device__ bf16 g_cn_lo[(size_t)Bb * Nn * Dd];
__device__ bf16 g_dat_hi[(size_t)Bb * Nn * Dd];
__device__ bf16 g_dat_lo[(size_t)Bb * Nn * Dd];
__device__ bf16 g_sim_hi[(size_t)Bb * Nn * Nn];
__device__ bf16 g_sim_lo[(size_t)Bb * Nn * Nn];
__device__ bf16 g_pe_hi[(size_t)Nn * Dd];
__device__ bf16 g_pe_lo[(size_t)Nn * Dd];
__device__ bf16 g_v_hi[(size_t)Bb * Nn * Nn];
__device__ bf16 g_v_lo[(size_t)Bb * Nn * Nn];
__device__ bf16 g_ctr_hi[(size_t)Bb * Nn * Dd];
__device__ bf16 g_ctr_lo[(size_t)Bb * Nn * Dd];
__device__ bf16 g_weT_hi[(size_t)Dd * Dd];
__device__ bf16 g_weT_lo[(size_t)Dd * Dd];
__device__ bf16 g_wmT_hi[(size_t)2 * Dd * Dd];
__device__ bf16 g_wmT_lo[(size_t)2 * Dd * Dd];
__device__ float g_csum[Bb * Nn];

// =================== helpers ===================

__device__ __forceinline__ void split2(float x, bf16& h, bf16& l) {
    h = __float2bfloat16(x);
    l = __float2bfloat16(x - __bfloat162float(h));
}

// swizzled smem offset within a 128x32-bf16 tile (row stride 64B, 4x 16B cols)
__device__ __forceinline__ uint32_t swz(uint32_t row, uint32_t col16) {
    return row * 64u + ((col16 ^ ((row >> 1) & 3u)) << 4);
}

__device__ __forceinline__ void cp16(uint32_t s, const void* g) {
    asm volatile("cp.async.cg.shared.global [%0], [%1], 16;" :: "r"(s), "l"(g));
}
__device__ __forceinline__ void cp_commit() {
    asm volatile("cp.async.commit_group;" ::: "memory");
}
__device__ __forceinline__ void cp_wait0() {
    asm volatile("cp.async.wait_group 0;" ::: "memory");
}

__device__ __forceinline__ void ldsm4(uint32_t& r0, uint32_t& r1, uint32_t& r2,
                                      uint32_t& r3, uint32_t a) {
    asm volatile("ldmatrix.sync.aligned.m8n8.x4.shared.b16 {%0,%1,%2,%3}, [%4];"
                 : "=r"(r0), "=r"(r1), "=r"(r2), "=r"(r3) : "r"(a));
}

__device__ __forceinline__ void mma_bf16(float* c, const uint32_t* a, const uint32_t* b) {
    asm volatile("mma.sync.aligned.m16n8k16.row.col.f32.bf16.bf16.f32 "
                 "{%0,%1,%2,%3}, {%4,%5,%6,%7}, {%8,%9}, {%0,%1,%2,%3};"
                 : "+f"(c[0]), "+f"(c[1]), "+f"(c[2]), "+f"(c[3])
                 : "r"(a[0]), "r"(a[1]), "r"(a[2]), "r"(a[3]), "r"(b[0]), "r"(b[1]));
}

// =================== MMA GEMM core ===================
// CTA tile 128(m) x 128(n), K-chunk 32. 8 warps: 4(m) x 2(n) -> warp 32m x 64n.
// smem: 2 stages x 4 tiles (Ah,Al,Bh,Bl) x 8KB = 64KB.
// 3-pass split accumulate: C += Ah*Bh + Ah*Bl + Al*Bh (fp32).

#define TILE_B   8192
#define STAGE_B  (4 * TILE_B)
#define SMEM_DYN (2 * STAGE_B)

// srcf(kc, P[4], ld[4]): P = row0/k0-adjusted pointers for Ah,Al,Bh,Bl (K-major)
template <typename SrcF>
__device__ __forceinline__ void mma_gemm(int KC, SrcF srcf, float c[2][8][4]) {
    extern __shared__ char smem[];
    const int tid = threadIdx.x;
    const int lane = tid & 31;
    const int wid = tid >> 5;
    const int wm = wid >> 1, wn = wid & 1;
    const uint32_t sbase = (uint32_t)__cvta_generic_to_shared(smem);

    auto load_stage = [&](int kc, int s) {
        const bf16* P[4]; int ld[4];
        srcf(kc, P, ld);
        const int row = tid >> 1;
        const int c0 = (tid & 1) * 2;
        #pragma unroll
        for (int t = 0; t < 4; ++t) {
            const bf16* src = P[t] + (size_t)row * ld[t] + c0 * 8;
            uint32_t dst = sbase + s * STAGE_B + t * TILE_B;
            cp16(dst + swz(row, c0),     src);
            cp16(dst + swz(row, c0 + 1), src + 8);
        }
    };

    auto compute = [&](int s) {
        const uint32_t base = sbase + s * STAGE_B;
        #pragma unroll
        for (int ks = 0; ks < 2; ++ks) {
            uint32_t ah[2][4], al[2][4], bh[8][2], bl[8][2];
            #pragma unroll
            for (int mi = 0; mi < 2; ++mi) {
                uint32_t row = wm * 32 + mi * 16 + (lane & 15);
                uint32_t col = ks * 2 + (lane >> 4);
                uint32_t off = swz(row, col);
                ldsm4(ah[mi][0], ah[mi][1], ah[mi][2], ah[mi][3], base + off);
                ldsm4(al[mi][0], al[mi][1], al[mi][2], al[mi][3], base + TILE_B + off);
            }
            #pragma unroll
            for (int j2 = 0; j2 < 4; ++j2) {
                uint32_t row = wn * 64 + j2 * 16 + ((lane >> 4) << 3) + (lane & 7);
                uint32_t col = ks * 2 + ((lane >> 3) & 1);
                uint32_t off = swz(row, col);
                ldsm4(bh[2 * j2][0], bh[2 * j2][1], bh[2 * j2 + 1][0], bh[2 * j2 + 1][1],
                      base + 2 * TILE_B + off);
                ldsm4(bl[2 * j2][0], bl[2 * j2][1], bl[2 * j2 + 1][0], bl[2 * j2 + 1][1],
                      base + 3 * TILE_B + off);
            }
            #pragma unroll
            for (int mi = 0; mi < 2; ++mi)
                #pragma unroll
                for (int nj = 0; nj < 8; ++nj)
                    mma_bf16(c[mi][nj], ah[mi], bh[nj]);
            #pragma unroll
            for (int mi = 0; mi < 2; ++mi)
                #pragma unroll
                for (int nj = 0; nj < 8; ++nj)
                    mma_bf16(c[mi][nj], ah[mi], bl[nj]);
            #pragma unroll
            for (int mi = 0; mi < 2; ++mi)
                #pragma unroll
                for (int nj = 0; nj < 8; ++nj)
                    mma_bf16(c[mi][nj], al[mi], bh[nj]);
        }
    };

    load_stage(0, 0);
    cp_commit();
    for (int kc = 0; kc < KC; ++kc) {
        const int s = kc & 1;
        cp_wait0();
        __syncthreads();
        if (kc + 1 < KC) { load_stage(kc + 1, s ^ 1); cp_commit(); }
        compute(s);
        __syncthreads();
    }
}

// epilogue iteration: calls body(row, col, v0, v1) for each accumulator pair
template <typename BodyF>
__device__ __forceinline__ void epi_loop(int m0, int n0, float c[2][8][4], BodyF body) {
    const int lane = threadIdx.x & 31;
    const int wid = threadIdx.x >> 5;
    const int wm = wid >> 1, wn = wid & 1;
    #pragma unroll
    for (int mi = 0; mi < 2; ++mi)
        #pragma unroll
        for (int nj = 0; nj < 8; ++nj)
            #pragma unroll
            for (int h = 0; h < 2; ++h) {
                const int row = m0 + wm * 32 + mi * 16 + (lane >> 2) + h * 8;
                const int col = n0 + wn * 64 + nj * 8 + (lane & 3) * 2;
                body(row, col, c[mi][nj][2 * h], c[mi][nj][2 * h + 1]);
            }
}

// =================== GEMM kernels ===================

// sim = relu(cn @ cn^T), split-stored
__global__ __launch_bounds__(256, 1) void k_mma_sim() {
    const int b = blockIdx.z, m0 = blockIdx.y * 128, n0 = blockIdx.x * 128;
    float c[2][8][4] = {};
    mma_gemm(Dd / 32,
        [&](int kc, const bf16** P, int* ld) {
            size_t a = ((size_t)b * Nn + m0) * Dd + kc * 32;
            size_t o = ((size_t)b * Nn + n0) * Dd + kc * 32;
            P[0] = g_cn_hi + a; P[1] = g_cn_lo + a;
            P[2] = g_cn_hi + o; P[3] = g_cn_lo + o;
            ld[0] = ld[1] = ld[2] = ld[3] = Dd;
        }, c);
    epi_loop(m0, n0, c, [&](int row, int col, float v0, float v1) {
        bf16 h0, l0, h1, l1;
        split2(fmaxf(v0, 0.f), h0, l0);
        split2(fmaxf(v1, 0.f), h1, l1);
        size_t o = ((size_t)b * Nn + row) * Nn + col;
        *(__nv_bfloat162*)(g_sim_hi + o) = __nv_bfloat162(h0, h1);
        *(__nv_bfloat162*)(g_sim_lo + o) = __nv_bfloat162(l0, l1);
    });
}

// v = posenc @ sim (sim symmetric: B[n][k] = sim[n][k])
__global__ __launch_bounds__(256, 1) void k_mma_v() {
    const int b = blockIdx.z, m0 = blockIdx.y * 128, n0 = blockIdx.x * 128;
    float c[2][8][4] = {};
    mma_gemm(Nn / 32,
        [&](int kc, const bf16** P, int* ld) {
            size_t a = (size_t)m0 * Dd + kc * 32;
            size_t o = ((size_t)b * Nn + n0) * Nn + kc * 32;
            P[0] = g_pe_hi + a; P[1] = g_pe_lo + a;
            P[2] = g_sim_hi + o; P[3] = g_sim_lo + o;
            ld[0] = ld[1] = Dd; ld[2] = ld[3] = Nn;
        }, c);
    epi_loop(m0, n0, c, [&](int row, int col, float v0, float v1) {
        bf16 h0, l0, h1, l1;
        split2(v0, h0, l0);
        split2(v1, h1, l1);
        size_t o = ((size_t)b * Nn + row) * Nn + col;
        *(__nv_bfloat162*)(g_v_hi + o) = __nv_bfloat162(h0, h1);
        *(__nv_bfloat162*)(g_v_lo + o) = __nv_bfloat162(l0, l1);
    });
}

// counter = softplus(v @ W_exp[1:] + csum*W_exp[0] + b_exp)
__global__ __launch_bounds__(256, 1) void k_mma_counter(const float* __restrict__ W_exp,
                                                        const float* __restrict__ b_exp) {
    const int b = blockIdx.z, m0 = blockIdx.y * 128, n0 = blockIdx.x * 128;
    float c[2][8][4] = {};
    mma_gemm(Nn / 32,
        [&](int kc, const bf16** P, int* ld) {
            size_t a = ((size_t)b * Nn + m0) * Nn + kc * 32;
            size_t o = (size_t)n0 * Dd + kc * 32;
            P[0] = g_v_hi + a; P[1] = g_v_lo + a;
            P[2] = g_weT_hi + o; P[3] = g_weT_lo + o;
            ld[0] = ld[1] = Nn; ld[2] = ld[3] = Dd;
        }, c);
    epi_loop(m0, n0, c, [&](int row, int col, float v0, float v1) {
        const float cs = g_csum[b * Nn + row];
        float x0 = v0 + cs * W_exp[col] + b_exp[col];
        float x1 = v1 + cs * W_exp[col + 1] + b_exp[col + 1];
        float s0 = fmaxf(x0, 0.f) + log1pf(expf(-fabsf(x0)));
        float s1 = fmaxf(x1, 0.f) + log1pf(expf(-fabsf(x1)));
        bf16 h0, l0, h1, l1;
        split2(s0, h0, l0);
        split2(s1, h1, l1);
        size_t o = ((size_t)b * Nn + row) * Dd + col;
        *(__nv_bfloat162*)(g_ctr_hi + o) = __nv_bfloat162(h0, h1);
        *(__nv_bfloat162*)(g_ctr_lo + o) = __nv_bfloat162(l0, l1);
    });
}

// out = data @ W_merge[:D] + counter @ W_merge[D:], fp32
__global__ __launch_bounds__(256, 1) void k_mma_out(float* __restrict__ outp) {
    const int b = blockIdx.z, m0 = blockIdx.y * 128, n0 = blockIdx.x * 128;
    float c[2][8][4] = {};
    mma_gemm(2 * Dd / 32,
        [&](int kc, const bf16** P, int* ld) {
            if (kc < Dd / 32) {
                size_t a = ((size_t)b * Nn + m0) * Dd + kc * 32;
                size_t o = (size_t)n0 * (2 * Dd) + kc * 32;
                P[0] = g_dat_hi + a; P[1] = g_dat_lo + a;
                P[2] = g_wmT_hi + o; P[3] = g_wmT_lo + o;
            } else {
                size_t a = ((size_t)b * Nn + m0) * Dd + (kc - Dd / 32) * 32;
                size_t o = (size_t)n0 * (2 * Dd) + Dd + (kc - Dd / 32) * 32;
                P[0] = g_ctr_hi + a; P[1] = g_ctr_lo + a;
                P[2] = g_wmT_hi + o; P[3] = g_wmT_lo + o;
            }
            ld[0] = ld[1] = Dd; ld[2] = ld[3] = 2 * Dd;
        }, c);
    epi_loop(m0, n0, c, [&](int row, int col, float v0, float v1) {
        size_t o = ((size_t)b * Nn + row) * Dd + col;
        float2 v; v.x = v0; v.y = v1;
        *(float2*)(outp + o) = v;
    });
}

// =================== prep / pointwise kernels ===================

__global__ __launch_bounds__(256) void k_prep_data(const float* __restrict__ data) {
    const int row = blockIdx.x;  // b*Nn + n
    const float* in = data + (size_t)row * Dd;
    float s = 0.f;
    for (int i = threadIdx.x; i < Dd; i += 256) { float v = in[i]; s += v * v; }
    __shared__ float red[32];
    #pragma unroll
    for (int o = 16; o; o >>= 1) s += __shfl_down_sync(0xffffffffu, s, o);
    if ((threadIdx.x & 31) == 0) red[threadIdx.x >> 5] = s;
    __syncthreads();
    if (threadIdx.x < 32) {
        float v = (threadIdx.x < 8) ? red[threadIdx.x] : 0.f;
        #pragma unroll
        for (int o = 4; o; o >>= 1) v += __shfl_down_sync(0xffffffffu, v, o);
        if (threadIdx.x == 0) red[0] = rsqrtf(fmaxf(v, 1e-12f));
    }
    __syncthreads();
    const float r = red[0];
    size_t base = (size_t)row * Dd;
    for (int i = threadIdx.x; i < Dd; i += 256) {
        float v = in[i];
        bf16 h, l;
        split2(v, h, l);
        g_dat_hi[base + i] = h; g_dat_lo[base + i] = l;
        split2(v * r, h, l);
        g_cn_hi[base + i] = h; g_cn_lo[base + i] = l;
    }
}

__global__ __launch_bounds__(256) void k_prep_pe() {
    const int idx = blockIdx.x * 256 + threadIdx.x;
    const int n = idx / Dd;
    const int i = idx - n * Dd;
    const float e = (float)(2 * (i / 2)) / (float)Dd;
    const float rate = 1.0f / powf(10000.0f, e);
    const float ang = (float)n * rate;
    float v = (i & 1) ? cosf(ang) : sinf(ang);
    bf16 h, l;
    split2(v, h, l);
    g_pe_hi[idx] = h; g_pe_lo[idx] = l;
}

// W_expT[n][k] = W_exp[(k+1)*Dd + n], split
__global__ void k_prep_weT(const float* __restrict__ W_exp) {
    __shared__ float t[32][33];
    const int x = blockIdx.x * 32 + threadIdx.x;  // n (src col)
    const int y = blockIdx.y * 32 + threadIdx.y;  // k (src row)
    t[threadIdx.y][threadIdx.x] = W_exp[(size_t)(y + 1) * Dd + x];
    __syncthreads();
    const int n = blockIdx.x * 32 + threadIdx.y;
    const int k = blockIdx.y * 32 + threadIdx.x;
    bf16 h, l;
    split2(t[threadIdx.x][threadIdx.y], h, l);
    g_weT_hi[(size_t)n * Dd + k] = h;
    g_weT_lo[(size_t)n * Dd + k] = l;
}

// W_mergeT[n][k] = W_merge[k*Dd + n], k in [0,4096), split
__global__ void k_prep_wmT(const float* __restrict__ W_merge) {
    __shared__ float t[32][33];
    const int x = blockIdx.x * 32 + threadIdx.x;  // n
    const int y = blockIdx.y * 32 + threadIdx.y;  // k
    t[threadIdx.y][threadIdx.x] = W_merge[(size_t)y * Dd + x];
    __syncthreads();
    const int n = blockIdx.x * 32 + threadIdx.y;
    const int k = blockIdx.y * 32 + threadIdx.x;
    bf16 h, l;
    split2(t[threadIdx.x][threadIdx.y], h, l);
    g_wmT_hi[(size_t)n * (2 * Dd) + k] = h;
    g_wmT_lo[(size_t)n * (2 * Dd) + k] = l;
}

__global__ __launch_bounds__(256) void k_rowsum() {
    const int row = blockIdx.x;  // b*Nn + n
    const bf16* sh = g_sim_hi + (size_t)row * Nn;
    const bf16* sl = g_sim_lo + (size_t)row * Nn;
    float acc = 0.f;
    for (int i = threadIdx.x; i < Nn; i += 256)
        acc += __bfloat162float(sh[i]) + __bfloat162float(sl[i]);
    __shared__ float red[32];
    #pragma unroll
    for (int o = 16; o; o >>= 1) acc += __shfl_down_sync(0xffffffffu, acc, o);
    if ((threadIdx.x & 31) == 0) red[threadIdx.x >> 5] = acc;
    __syncthreads();
    if (threadIdx.x < 32) {
        float v = (threadIdx.x < 8) ? red[threadIdx.x] : 0.f;
        #pragma unroll
        for (int o = 4; o; o >>= 1) v += __shfl_down_sync(0xffffffffu, v, o);
        if (threadIdx.x == 0) g_csum[row] = v;
    }
}

// =================== launch ===================

extern "C" void kernel_launch(void* const* d_in, const int* in_sizes, int n_in,
                              void* d_out, int out_size) {
    const float* data    = (const float*)d_in[0];
    const float* W_exp   = (const float*)d_in[1];
    const float* b_exp   = (const float*)d_in[2];
    const float* W_merge = (const float*)d_in[3];
    float* out = (float*)d_out;
    (void)in_sizes; (void)n_in; (void)out_size;

    cudaFuncSetAttribute(k_mma_sim,     cudaFuncAttributeMaxDynamicSharedMemorySize, SMEM_DYN);
    cudaFuncSetAttribute(k_mma_v,       cudaFuncAttributeMaxDynamicSharedMemorySize, SMEM_DYN);
    cudaFuncSetAttribute(k_mma_counter, cudaFuncAttributeMaxDynamicSharedMemorySize, SMEM_DYN);
    cudaFuncSetAttribute(k_mma_out,     cudaFuncAttributeMaxDynamicSharedMemorySize, SMEM_DYN);

    const dim3 tgrid(Nn / 128, Nn / 128, Bb);

    k_prep_data<<<Bb * Nn, 256>>>(data);
    k_prep_pe<<<(Nn * Dd) / 256, 256>>>();
    k_prep_weT<<<dim3(Dd / 32, Dd / 32), dim3(32, 32)>>>(W_exp);
    k_prep_wmT<<<dim3(Dd / 32, (2 * Dd) / 32), dim3(32, 32)>>>(W_merge);

    k_mma_sim<<<tgrid, 256, SMEM_DYN>>>();
    k_rowsum<<<Bb * Nn, 256>>>();
    k_mma_v<<<tgrid, 256, SMEM_DYN>>>();
    k_mma_counter<<<tgrid, 256, SMEM_DYN>>>(W_exp, b_exp);
    k_mma_out<<<tgrid, 256, SMEM_DYN>>>(out);
}

// round 5
// speedup vs baseline: 4.0269x; 1.0927x over previous
#include <cuda_runtime.h>
#include <cuda_bf16.h>
#include <math.h>
#include <stdint.h>

#define Bb 4
#define Nn 2048
#define Dd 2048
typedef __nv_bfloat16 bf16;

// ---- scratch (static __device__; no allocations allowed) ----
__device__ bf16 g_cn_hi[(size_t)Bb * Nn * Dd];
__device__ bf16 g_cn_lo[(size_t)Bb * Nn * Dd];
__device__ bf16 g_dat_hi[(size_t)Bb * Nn * Dd];
__device__ bf16 g_dat_lo[(size_t)Bb * Nn * Dd];
__device__ bf16 g_sim_hi[(size_t)Bb * Nn * Nn];
__device__ bf16 g_sim_lo[(size_t)Bb * Nn * Nn];
__device__ bf16 g_pe_hi[(size_t)Nn * Dd];
__device__ bf16 g_pe_lo[(size_t)Nn * Dd];
__device__ bf16 g_v_hi[(size_t)Bb * Nn * Nn];
__device__ bf16 g_v_lo[(size_t)Bb * Nn * Nn];
__device__ bf16 g_ctr_hi[(size_t)Bb * Nn * Dd];
__device__ bf16 g_ctr_lo[(size_t)Bb * Nn * Dd];
__device__ bf16 g_weT_hi[(size_t)Dd * Dd];
__device__ bf16 g_weT_lo[(size_t)Dd * Dd];
__device__ bf16 g_wmT_hi[(size_t)2 * Dd * Dd];
__device__ bf16 g_wmT_lo[(size_t)2 * Dd * Dd];
__device__ float g_csum[Bb * Nn];

// =================== helpers ===================

__device__ __forceinline__ void split2(float x, bf16& h, bf16& l) {
    h = __float2bfloat16(x);
    l = __float2bfloat16(x - __bfloat162float(h));
}

// swizzled smem offset within a 128x32-bf16 tile (row stride 64B, 4x 16B cols)
__device__ __forceinline__ uint32_t swz(uint32_t row, uint32_t col16) {
    return row * 64u + ((col16 ^ ((row >> 1) & 3u)) << 4);
}

__device__ __forceinline__ void cp16(uint32_t s, const void* g) {
    asm volatile("cp.async.cg.shared.global [%0], [%1], 16;" :: "r"(s), "l"(g));
}
__device__ __forceinline__ void cp_commit() {
    asm volatile("cp.async.commit_group;" ::: "memory");
}
__device__ __forceinline__ void cp_wait2() {
    asm volatile("cp.async.wait_group 2;" ::: "memory");
}

__device__ __forceinline__ void ldsm4(uint32_t& r0, uint32_t& r1, uint32_t& r2,
                                      uint32_t& r3, uint32_t a) {
    asm volatile("ldmatrix.sync.aligned.m8n8.x4.shared.b16 {%0,%1,%2,%3}, [%4];"
                 : "=r"(r0), "=r"(r1), "=r"(r2), "=r"(r3) : "r"(a));
}

__device__ __forceinline__ void mma_bf16(float* c, const uint32_t* a, const uint32_t* b) {
    asm volatile("mma.sync.aligned.m16n8k16.row.col.f32.bf16.bf16.f32 "
                 "{%0,%1,%2,%3}, {%4,%5,%6,%7}, {%8,%9}, {%0,%1,%2,%3};"
                 : "+f"(c[0]), "+f"(c[1]), "+f"(c[2]), "+f"(c[3])
                 : "r"(a[0]), "r"(a[1]), "r"(a[2]), "r"(a[3]), "r"(b[0]), "r"(b[1]));
}

// =================== MMA GEMM core ===================
// CTA tile 128(m) x 128(n), K-chunk 32. 8 warps: 4(m) x 2(n) -> warp 32m x 64n.
// smem: 4 stages x 4 tiles (Ah,Al,Bh,Bl) x 8KB = 128KB. wait_group 2.
// 3-pass split accumulate: C += Ah*Bh + Ah*Bl + Al*Bh (fp32).

#define TILE_B   8192
#define STAGE_B  (4 * TILE_B)
#define NSTAGE   4
#define SMEM_DYN (NSTAGE * STAGE_B)

// srcf(kc, P[4], ld[4]): P = row0/k0-adjusted pointers for Ah,Al,Bh,Bl (K-major)
template <typename SrcF>
__device__ __forceinline__ void mma_gemm(int KC, SrcF srcf, float c[2][8][4]) {
    extern __shared__ char smem[];
    const int tid = threadIdx.x;
    const int lane = tid & 31;
    const int wid = tid >> 5;
    const int wm = wid >> 1, wn = wid & 1;
    const uint32_t sbase = (uint32_t)__cvta_generic_to_shared(smem);

    auto load_stage = [&](int kc, int s) {
        const bf16* P[4]; int ld[4];
        srcf(kc, P, ld);
        const int row = tid >> 1;
        const int c0 = (tid & 1) * 2;
        #pragma unroll
        for (int t = 0; t < 4; ++t) {
            const bf16* src = P[t] + (size_t)row * ld[t] + c0 * 8;
            uint32_t dst = sbase + s * STAGE_B + t * TILE_B;
            cp16(dst + swz(row, c0),     src);
            cp16(dst + swz(row, c0 + 1), src + 8);
        }
    };

    auto compute = [&](int s) {
        const uint32_t base = sbase + s * STAGE_B;
        #pragma unroll
        for (int ks = 0; ks < 2; ++ks) {
            uint32_t ah[2][4], al[2][4], bh[8][2], bl[8][2];
            #pragma unroll
            for (int mi = 0; mi < 2; ++mi) {
                uint32_t row = wm * 32 + mi * 16 + (lane & 15);
                uint32_t col = ks * 2 + (lane >> 4);
                uint32_t off = swz(row, col);
                ldsm4(ah[mi][0], ah[mi][1], ah[mi][2], ah[mi][3], base + off);
                ldsm4(al[mi][0], al[mi][1], al[mi][2], al[mi][3], base + TILE_B + off);
            }
            #pragma unroll
            for (int j2 = 0; j2 < 4; ++j2) {
                uint32_t row = wn * 64 + j2 * 16 + ((lane >> 4) << 3) + (lane & 7);
                uint32_t col = ks * 2 + ((lane >> 3) & 1);
                uint32_t off = swz(row, col);
                ldsm4(bh[2 * j2][0], bh[2 * j2][1], bh[2 * j2 + 1][0], bh[2 * j2 + 1][1],
                      base + 2 * TILE_B + off);
                ldsm4(bl[2 * j2][0], bl[2 * j2][1], bl[2 * j2 + 1][0], bl[2 * j2 + 1][1],
                      base + 3 * TILE_B + off);
            }
            #pragma unroll
            for (int mi = 0; mi < 2; ++mi)
                #pragma unroll
                for (int nj = 0; nj < 8; ++nj)
                    mma_bf16(c[mi][nj], ah[mi], bh[nj]);
            #pragma unroll
            for (int mi = 0; mi < 2; ++mi)
                #pragma unroll
                for (int nj = 0; nj < 8; ++nj)
                    mma_bf16(c[mi][nj], ah[mi], bl[nj]);
            #pragma unroll
            for (int mi = 0; mi < 2; ++mi)
                #pragma unroll
                for (int nj = 0; nj < 8; ++nj)
                    mma_bf16(c[mi][nj], al[mi], bh[nj]);
        }
    };

    // prefetch 3 stages
    #pragma unroll
    for (int p = 0; p < NSTAGE - 1; ++p) {
        if (p < KC) load_stage(p, p);
        cp_commit();
    }
    for (int kc = 0; kc < KC; ++kc) {
        cp_wait2();          // oldest outstanding group (stage kc&3) complete
        __syncthreads();     // all warps past previous compute before reloading
        const int pf = kc + NSTAGE - 1;
        if (pf < KC) load_stage(pf, pf & (NSTAGE - 1));
        cp_commit();
        compute(kc & (NSTAGE - 1));
    }
    __syncthreads();         // smem safe for epilogue reuse
}

// epilogue iteration: calls body(row, col, v0, v1) for each accumulator pair
template <typename BodyF>
__device__ __forceinline__ void epi_loop(int m0, int n0, float c[2][8][4], BodyF body) {
    const int lane = threadIdx.x & 31;
    const int wid = threadIdx.x >> 5;
    const int wm = wid >> 1, wn = wid & 1;
    #pragma unroll
    for (int mi = 0; mi < 2; ++mi)
        #pragma unroll
        for (int nj = 0; nj < 8; ++nj)
            #pragma unroll
            for (int h = 0; h < 2; ++h) {
                const int row = m0 + wm * 32 + mi * 16 + (lane >> 2) + h * 8;
                const int col = n0 + wn * 64 + nj * 8 + (lane & 3) * 2;
                body(row, col, c[mi][nj][2 * h], c[mi][nj][2 * h + 1]);
            }
}

// =================== GEMM kernels ===================

// sim = relu(cn @ cn^T), split-stored, symmetric: only upper-tri tiles computed,
// mirrored through padded smem. grid.x = 136 (= 16*17/2)
#define EPAD 136  // smem epilogue tile row stride (elements); 272B, 16B-aligned
__global__ __launch_bounds__(256, 1) void k_mma_sim() {
    const int b = blockIdx.z;
    int t = blockIdx.x, ti = 0;
    while (t >= 16 - ti) { t -= 16 - ti; ++ti; }
    const int tj = ti + t;
    const int m0 = ti * 128, n0 = tj * 128;

    float c[2][8][4] = {};
    mma_gemm(Dd / 32,
        [&](int kc, const bf16** P, int* ld) {
            size_t a = ((size_t)b * Nn + m0) * Dd + kc * 32;
            size_t o = ((size_t)b * Nn + n0) * Dd + kc * 32;
            P[0] = g_cn_hi + a; P[1] = g_cn_lo + a;
            P[2] = g_cn_hi + o; P[3] = g_cn_lo + o;
            ld[0] = ld[1] = ld[2] = ld[3] = Dd;
        }, c);

    // stage relu+split tile into padded smem
    extern __shared__ char smem[];
    bf16* sh = (bf16*)smem;                       // [128][EPAD]
    bf16* sl = (bf16*)(smem + 128 * EPAD * 2);    // [128][EPAD]
    epi_loop(0, 0, c, [&](int r, int col, float v0, float v1) {
        bf16 h0, l0, h1, l1;
        split2(fmaxf(v0, 0.f), h0, l0);
        split2(fmaxf(v1, 0.f), h1, l1);
        sh[r * EPAD + col] = h0; sh[r * EPAD + col + 1] = h1;
        sl[r * EPAD + col] = l0; sl[r * EPAD + col + 1] = l1;
    });
    __syncthreads();

    // normal orientation: sim[m0+r][n0+c]
    for (int idx = threadIdx.x; idx < 128 * 16; idx += 256) {
        const int r = idx >> 4, seg = idx & 15;
        size_t o = ((size_t)b * Nn + m0 + r) * Nn + n0 + seg * 8;
        *(uint4*)(g_sim_hi + o) = *(const uint4*)(sh + r * EPAD + seg * 8);
        *(uint4*)(g_sim_lo + o) = *(const uint4*)(sl + r * EPAD + seg * 8);
    }
    // mirrored orientation: sim[n0+c][m0+r] (skip on diagonal tiles)
    if (ti != tj) {
        for (int idx = threadIdx.x; idx < 128 * 16; idx += 256) {
            const int cc = idx >> 4, rseg = idx & 15;
            bf16 th[8], tl[8];
            #pragma unroll
            for (int q = 0; q < 8; ++q) {
                th[q] = sh[(rseg * 8 + q) * EPAD + cc];
                tl[q] = sl[(rseg * 8 + q) * EPAD + cc];
            }
            size_t o = ((size_t)b * Nn + n0 + cc) * Nn + m0 + rseg * 8;
            *(uint4*)(g_sim_hi + o) = *(const uint4*)th;
            *(uint4*)(g_sim_lo + o) = *(const uint4*)tl;
        }
    }
}

// v = posenc @ sim (sim symmetric: B[n][k] = sim[n][k])
__global__ __launch_bounds__(256, 1) void k_mma_v() {
    const int b = blockIdx.z, m0 = blockIdx.y * 128, n0 = blockIdx.x * 128;
    float c[2][8][4] = {};
    mma_gemm(Nn / 32,
        [&](int kc, const bf16** P, int* ld) {
            size_t a = (size_t)m0 * Dd + kc * 32;
            size_t o = ((size_t)b * Nn + n0) * Nn + kc * 32;
            P[0] = g_pe_hi + a; P[1] = g_pe_lo + a;
            P[2] = g_sim_hi + o; P[3] = g_sim_lo + o;
            ld[0] = ld[1] = Dd; ld[2] = ld[3] = Nn;
        }, c);
    epi_loop(m0, n0, c, [&](int row, int col, float v0, float v1) {
        bf16 h0, l0, h1, l1;
        split2(v0, h0, l0);
        split2(v1, h1, l1);
        size_t o = ((size_t)b * Nn + row) * Nn + col;
        *(__nv_bfloat162*)(g_v_hi + o) = __nv_bfloat162(h0, h1);
        *(__nv_bfloat162*)(g_v_lo + o) = __nv_bfloat162(l0, l1);
    });
}

// counter = softplus(v @ W_exp[1:] + csum*W_exp[0] + b_exp)
__global__ __launch_bounds__(256, 1) void k_mma_counter(const float* __restrict__ W_exp,
                                                        const float* __restrict__ b_exp) {
    const int b = blockIdx.z, m0 = blockIdx.y * 128, n0 = blockIdx.x * 128;
    float c[2][8][4] = {};
    mma_gemm(Nn / 32,
        [&](int kc, const bf16** P, int* ld) {
            size_t a = ((size_t)b * Nn + m0) * Nn + kc * 32;
            size_t o = (size_t)n0 * Dd + kc * 32;
            P[0] = g_v_hi + a; P[1] = g_v_lo + a;
            P[2] = g_weT_hi + o; P[3] = g_weT_lo + o;
            ld[0] = ld[1] = Nn; ld[2] = ld[3] = Dd;
        }, c);
    epi_loop(m0, n0, c, [&](int row, int col, float v0, float v1) {
        const float cs = g_csum[b * Nn + row];
        float x0 = v0 + cs * W_exp[col] + b_exp[col];
        float x1 = v1 + cs * W_exp[col + 1] + b_exp[col + 1];
        float s0 = fmaxf(x0, 0.f) + log1pf(expf(-fabsf(x0)));
        float s1 = fmaxf(x1, 0.f) + log1pf(expf(-fabsf(x1)));
        bf16 h0, l0, h1, l1;
        split2(s0, h0, l0);
        split2(s1, h1, l1);
        size_t o = ((size_t)b * Nn + row) * Dd + col;
        *(__nv_bfloat162*)(g_ctr_hi + o) = __nv_bfloat162(h0, h1);
        *(__nv_bfloat162*)(g_ctr_lo + o) = __nv_bfloat162(l0, l1);
    });
}

// out = data @ W_merge[:D] + counter @ W_merge[D:], fp32
__global__ __launch_bounds__(256, 1) void k_mma_out(float* __restrict__ outp) {
    const int b = blockIdx.z, m0 = blockIdx.y * 128, n0 = blockIdx.x * 128;
    float c[2][8][4] = {};
    mma_gemm(2 * Dd / 32,
        [&](int kc, const bf16** P, int* ld) {
            if (kc < Dd / 32) {
                size_t a = ((size_t)b * Nn + m0) * Dd + kc * 32;
                size_t o = (size_t)n0 * (2 * Dd) + kc * 32;
                P[0] = g_dat_hi + a; P[1] = g_dat_lo + a;
                P[2] = g_wmT_hi + o; P[3] = g_wmT_lo + o;
            } else {
                size_t a = ((size_t)b * Nn + m0) * Dd + (kc - Dd / 32) * 32;
                size_t o = (size_t)n0 * (2 * Dd) + Dd + (kc - Dd / 32) * 32;
                P[0] = g_ctr_hi + a; P[1] = g_ctr_lo + a;
                P[2] = g_wmT_hi + o; P[3] = g_wmT_lo + o;
            }
            ld[0] = ld[1] = Dd; ld[2] = ld[3] = 2 * Dd;
        }, c);
    epi_loop(m0, n0, c, [&](int row, int col, float v0, float v1) {
        size_t o = ((size_t)b * Nn + row) * Dd + col;
        float2 v; v.x = v0; v.y = v1;
        *(float2*)(outp + o) = v;
    });
}

// =================== prep / pointwise kernels ===================

__global__ __launch_bounds__(256) void k_prep_data(const float* __restrict__ data) {
    const int row = blockIdx.x;  // b*Nn + n
    const float* in = data + (size_t)row * Dd;
    float s = 0.f;
    for (int i = threadIdx.x; i < Dd; i += 256) { float v = in[i]; s += v * v; }
    __shared__ float red[32];
    #pragma unroll
    for (int o = 16; o; o >>= 1) s += __shfl_down_sync(0xffffffffu, s, o);
    if ((threadIdx.x & 31) == 0) red[threadIdx.x >> 5] = s;
    __syncthreads();
    if (threadIdx.x < 32) {
        float v = (threadIdx.x < 8) ? red[threadIdx.x] : 0.f;
        #pragma unroll
        for (int o = 4; o; o >>= 1) v += __shfl_down_sync(0xffffffffu, v, o);
        if (threadIdx.x == 0) red[0] = rsqrtf(fmaxf(v, 1e-12f));
    }
    __syncthreads();
    const float r = red[0];
    size_t base = (size_t)row * Dd;
    for (int i = threadIdx.x; i < Dd; i += 256) {
        float v = in[i];
        bf16 h, l;
        split2(v, h, l);
        g_dat_hi[base + i] = h; g_dat_lo[base + i] = l;
        split2(v * r, h, l);
        g_cn_hi[base + i] = h; g_cn_lo[base + i] = l;
    }
}

__global__ __launch_bounds__(256) void k_prep_pe() {
    const int idx = blockIdx.x * 256 + threadIdx.x;
    const int n = idx / Dd;
    const int i = idx - n * Dd;
    const float e = (float)(2 * (i / 2)) / (float)Dd;
    const float rate = 1.0f / powf(10000.0f, e);
    const float ang = (float)n * rate;
    float v = (i & 1) ? cosf(ang) : sinf(ang);
    bf16 h, l;
    split2(v, h, l);
    g_pe_hi[idx] = h; g_pe_lo[idx] = l;
}

// W_expT[n][k] = W_exp[(k+1)*Dd + n], split
__global__ void k_prep_weT(const float* __restrict__ W_exp) {
    __shared__ float t[32][33];
    const int x = blockIdx.x * 32 + threadIdx.x;  // n (src col)
    const int y = blockIdx.y * 32 + threadIdx.y;  // k (src row)
    t[threadIdx.y][threadIdx.x] = W_exp[(size_t)(y + 1) * Dd + x];
    __syncthreads();
    const int n = blockIdx.x * 32 + threadIdx.y;
    const int k = blockIdx.y * 32 + threadIdx.x;
    bf16 h, l;
    split2(t[threadIdx.x][threadIdx.y], h, l);
    g_weT_hi[(size_t)n * Dd + k] = h;
    g_weT_lo[(size_t)n * Dd + k] = l;
}

// W_mergeT[n][k] = W_merge[k*Dd + n], k in [0,4096), split
__global__ void k_prep_wmT(const float* __restrict__ W_merge) {
    __shared__ float t[32][33];
    const int x = blockIdx.x * 32 + threadIdx.x;  // n
    const int y = blockIdx.y * 32 + threadIdx.y;  // k
    t[threadIdx.y][threadIdx.x] = W_merge[(size_t)y * Dd + x];
    __syncthreads();
    const int n = blockIdx.x * 32 + threadIdx.y;
    const int k = blockIdx.y * 32 + threadIdx.x;
    bf16 h, l;
    split2(t[threadIdx.x][threadIdx.y], h, l);
    g_wmT_hi[(size_t)n * (2 * Dd) + k] = h;
    g_wmT_lo[(size_t)n * (2 * Dd) + k] = l;
}

__global__ __launch_bounds__(256) void k_rowsum() {
    const int row = blockIdx.x;  // b*Nn + n
    const bf16* sh = g_sim_hi + (size_t)row * Nn;
    const bf16* sl = g_sim_lo + (size_t)row * Nn;
    float acc = 0.f;
    for (int i = threadIdx.x; i < Nn; i += 256)
        acc += __bfloat162float(sh[i]) + __bfloat162float(sl[i]);
    __shared__ float red[32];
    #pragma unroll
    for (int o = 16; o; o >>= 1) acc += __shfl_down_sync(0xffffffffu, acc, o);
    if ((threadIdx.x & 31) == 0) red[threadIdx.x >> 5] = acc;
    __syncthreads();
    if (threadIdx.x < 32) {
        float v = (threadIdx.x < 8) ? red[threadIdx.x] : 0.f;
        #pragma unroll
        for (int o = 4; o; o >>= 1) v += __shfl_down_sync(0xffffffffu, v, o);
        if (threadIdx.x == 0) g_csum[row] = v;
    }
}

// =================== launch ===================

extern "C" void kernel_launch(void* const* d_in, const int* in_sizes, int n_in,
                              void* d_out, int out_size) {
    const float* data    = (const float*)d_in[0];
    const float* W_exp   = (const float*)d_in[1];
    const float* b_exp   = (const float*)d_in[2];
    const float* W_merge = (const float*)d_in[3];
    float* out = (float*)d_out;
    (void)in_sizes; (void)n_in; (void)out_size;

    cudaFuncSetAttribute(k_mma_sim,     cudaFuncAttributeMaxDynamicSharedMemorySize, SMEM_DYN);
    cudaFuncSetAttribute(k_mma_v,       cudaFuncAttributeMaxDynamicSharedMemorySize, SMEM_DYN);
    cudaFuncSetAttribute(k_mma_counter, cudaFuncAttributeMaxDynamicSharedMemorySize, SMEM_DYN);
    cudaFuncSetAttribute(k_mma_out,     cudaFuncAttributeMaxDynamicSharedMemorySize, SMEM_DYN);

    const dim3 tgrid(Nn / 128, Nn / 128, Bb);

    k_prep_data<<<Bb * Nn, 256>>>(data);
    k_prep_pe<<<(Nn * Dd) / 256, 256>>>();
    k_prep_weT<<<dim3(Dd / 32, Dd / 32), dim3(32, 32)>>>(W_exp);
    k_prep_wmT<<<dim3(Dd / 32, (2 * Dd) / 32), dim3(32, 32)>>>(W_merge);

    k_mma_sim<<<dim3(136, 1, Bb), 256, SMEM_DYN>>>();
    k_rowsum<<<Bb * Nn, 256>>>();
    k_mma_v<<<tgrid, 256, SMEM_DYN>>>();
    k_mma_counter<<<tgrid, 256, SMEM_DYN>>>(W_exp, b_exp);
    k_mma_out<<<tgrid, 256, SMEM_DYN>>>(out);
}

// round 6
// speedup vs baseline: 5.4904x; 1.3634x over previous
#include <cuda_runtime.h>
#include <cuda_fp16.h>
#include <math.h>
#include <stdint.h>

#define Bb 4
#define Nn 2048
#define Dd 2048
typedef __half f16;

// ---- scratch (static __device__; no allocations allowed) ----
__device__ f16 g_cn_hi[(size_t)Bb * Nn * Dd];
__device__ f16 g_cn_lo[(size_t)Bb * Nn * Dd];
__device__ f16 g_dat_hi[(size_t)Bb * Nn * Dd];
__device__ f16 g_dat_lo[(size_t)Bb * Nn * Dd];
__device__ f16 g_sim_hi[(size_t)Bb * Nn * Nn];
__device__ f16 g_sim_lo[(size_t)Bb * Nn * Nn];   // only rowsum reads lo
__device__ f16 g_pe_hi[(size_t)Nn * Dd];
__device__ f16 g_pe_lo[(size_t)Nn * Dd];
__device__ f16 g_v_hi[(size_t)Bb * Nn * Nn];
__device__ f16 g_v_lo[(size_t)Bb * Nn * Nn];
__device__ f16 g_ctr_hi[(size_t)Bb * Nn * Dd];
__device__ f16 g_ctr_lo[(size_t)Bb * Nn * Dd];
__device__ f16 g_weT_hi[(size_t)Dd * Dd];        // B-role only: hi only
__device__ f16 g_wmT_hi[(size_t)2 * Dd * Dd];    // B-role only: hi only
__device__ float g_csum[Bb * Nn];

// =================== helpers ===================

__device__ __forceinline__ void split2(float x, f16& h, f16& l) {
    h = __float2half_rn(x);
    l = __float2half_rn(x - __half2float(h));
}

__device__ __forceinline__ void cp16(uint32_t s, const void* g) {
    asm volatile("cp.async.cg.shared.global [%0], [%1], 16;" :: "r"(s), "l"(g));
}
__device__ __forceinline__ void cp_commit() {
    asm volatile("cp.async.commit_group;" ::: "memory");
}
__device__ __forceinline__ void cp_wait2() {
    asm volatile("cp.async.wait_group 2;" ::: "memory");
}

__device__ __forceinline__ void ldsm4(uint32_t& r0, uint32_t& r1, uint32_t& r2,
                                      uint32_t& r3, uint32_t a) {
    asm volatile("ldmatrix.sync.aligned.m8n8.x4.shared.b16 {%0,%1,%2,%3}, [%4];"
                 : "=r"(r0), "=r"(r1), "=r"(r2), "=r"(r3) : "r"(a));
}

__device__ __forceinline__ void mma_f16(float* c, const uint32_t* a, const uint32_t* b) {
    asm volatile("mma.sync.aligned.m16n8k16.row.col.f32.f16.f16.f32 "
                 "{%0,%1,%2,%3}, {%4,%5,%6,%7}, {%8,%9}, {%0,%1,%2,%3};"
                 : "+f"(c[0]), "+f"(c[1]), "+f"(c[2]), "+f"(c[3])
                 : "r"(a[0]), "r"(a[1]), "r"(a[2]), "r"(a[3]), "r"(b[0]), "r"(b[1]));
}

// =================== MMA GEMM core ===================
// CTA tile 128(m) x 128(n), K-chunk 64. 8 warps: 4(m) x 2(n) -> warp 32m x 64n.
// Tiles per stage: Ah, Al, Bh (128x64 fp16 = 16KB each) = 48KB; 4 stages = 192KB.
// 2-pass split accumulate: C += Ah*Bh + Al*Bh  (= A_full * B_hi, fp32 acc).

#define TILE_B   16384
#define STAGE_B  (3 * TILE_B)
#define NSTAGE   4
#define SMEM_DYN (NSTAGE * STAGE_B)   // 196608

// 8-way XOR swizzle within 128x64-f16 tile (row stride 128B = 8x16B cols)
__device__ __forceinline__ uint32_t swz64(uint32_t row, uint32_t c16) {
    return row * 128u + ((c16 ^ (row & 7u)) << 4);
}

// srcf(kc, P[3], ld[3]): pointers for Ah, Al, Bh at this K-chunk (K-major)
template <typename SrcF>
__device__ __forceinline__ void mma_gemm(int KC, SrcF srcf, float c[2][8][4]) {
    extern __shared__ char smem[];
    const int tid = threadIdx.x;
    const int lane = tid & 31;
    const int wid = tid >> 5;
    const int wm = wid >> 1, wn = wid & 1;
    const uint32_t sbase = (uint32_t)__cvta_generic_to_shared(smem);

    auto load_stage = [&](int kc, int s) {
        const f16* P[3]; int ld[3];
        srcf(kc, P, ld);
        const int row = tid >> 1;
        const int c0 = (tid & 1) * 4;
        #pragma unroll
        for (int t = 0; t < 3; ++t) {
            const f16* src = P[t] + (size_t)row * ld[t] + c0 * 8;
            uint32_t dst = sbase + s * STAGE_B + t * TILE_B + row * 128u;
            #pragma unroll
            for (int q = 0; q < 4; ++q)
                cp16(dst + ((uint32_t)((c0 + q) ^ (row & 7)) << 4), src + q * 8);
        }
    };

    auto compute = [&](int s) {
        const uint32_t base = sbase + s * STAGE_B;
        #pragma unroll
        for (int ks = 0; ks < 4; ++ks) {
            uint32_t ah[2][4], al[2][4], bh[8][2];
            #pragma unroll
            for (int mi = 0; mi < 2; ++mi) {
                uint32_t row = wm * 32 + mi * 16 + (lane & 15);
                uint32_t c16 = ks * 2 + (lane >> 4);
                uint32_t off = swz64(row, c16);
                ldsm4(ah[mi][0], ah[mi][1], ah[mi][2], ah[mi][3], base + off);
                ldsm4(al[mi][0], al[mi][1], al[mi][2], al[mi][3], base + TILE_B + off);
            }
            #pragma unroll
            for (int j2 = 0; j2 < 4; ++j2) {
                uint32_t row = wn * 64 + j2 * 16 + ((lane >> 4) << 3) + (lane & 7);
                uint32_t c16 = ks * 2 + ((lane >> 3) & 1);
                uint32_t off = swz64(row, c16);
                ldsm4(bh[2 * j2][0], bh[2 * j2][1], bh[2 * j2 + 1][0], bh[2 * j2 + 1][1],
                      base + 2 * TILE_B + off);
            }
            #pragma unroll
            for (int mi = 0; mi < 2; ++mi)
                #pragma unroll
                for (int nj = 0; nj < 8; ++nj)
                    mma_f16(c[mi][nj], ah[mi], bh[nj]);
            #pragma unroll
            for (int mi = 0; mi < 2; ++mi)
                #pragma unroll
                for (int nj = 0; nj < 8; ++nj)
                    mma_f16(c[mi][nj], al[mi], bh[nj]);
        }
    };

    // prefetch 3 stages
    #pragma unroll
    for (int p = 0; p < NSTAGE - 1; ++p) {
        if (p < KC) load_stage(p, p);
        cp_commit();
    }
    for (int kc = 0; kc < KC; ++kc) {
        cp_wait2();          // oldest outstanding group (stage kc) complete
        __syncthreads();     // all warps past compute of stage (kc-1)&3 before reload
        const int pf = kc + NSTAGE - 1;
        if (pf < KC) load_stage(pf, pf & (NSTAGE - 1));
        cp_commit();
        compute(kc & (NSTAGE - 1));
    }
    __syncthreads();         // smem safe for epilogue reuse
}

// epilogue iteration: calls body(row, col, v0, v1) for each accumulator pair
template <typename BodyF>
__device__ __forceinline__ void epi_loop(int m0, int n0, float c[2][8][4], BodyF body) {
    const int lane = threadIdx.x & 31;
    const int wid = threadIdx.x >> 5;
    const int wm = wid >> 1, wn = wid & 1;
    #pragma unroll
    for (int mi = 0; mi < 2; ++mi)
        #pragma unroll
        for (int nj = 0; nj < 8; ++nj)
            #pragma unroll
            for (int h = 0; h < 2; ++h) {
                const int row = m0 + wm * 32 + mi * 16 + (lane >> 2) + h * 8;
                const int col = n0 + wn * 64 + nj * 8 + (lane & 3) * 2;
                body(row, col, c[mi][nj][2 * h], c[mi][nj][2 * h + 1]);
            }
}

// =================== GEMM kernels ===================

// sim = relu(cn @ cn^T), split-stored, symmetric: only upper-tri tiles computed,
// mirrored through padded smem. grid.x = 136 (= 16*17/2)
#define EPAD 136
__global__ __launch_bounds__(256, 1) void k_mma_sim() {
    const int b = blockIdx.z;
    int t = blockIdx.x, ti = 0;
    while (t >= 16 - ti) { t -= 16 - ti; ++ti; }
    const int tj = ti + t;
    const int m0 = ti * 128, n0 = tj * 128;

    float c[2][8][4] = {};
    mma_gemm(Dd / 64,
        [&](int kc, const f16** P, int* ld) {
            size_t a = ((size_t)b * Nn + m0) * Dd + kc * 64;
            size_t o = ((size_t)b * Nn + n0) * Dd + kc * 64;
            P[0] = g_cn_hi + a; P[1] = g_cn_lo + a; P[2] = g_cn_hi + o;
            ld[0] = ld[1] = ld[2] = Dd;
        }, c);

    extern __shared__ char smem[];
    f16* sh = (f16*)smem;                       // [128][EPAD]
    f16* sl = (f16*)(smem + 128 * EPAD * 2);    // [128][EPAD]
    epi_loop(0, 0, c, [&](int r, int col, float v0, float v1) {
        f16 h0, l0, h1, l1;
        split2(fmaxf(v0, 0.f), h0, l0);
        split2(fmaxf(v1, 0.f), h1, l1);
        sh[r * EPAD + col] = h0; sh[r * EPAD + col + 1] = h1;
        sl[r * EPAD + col] = l0; sl[r * EPAD + col + 1] = l1;
    });
    __syncthreads();

    for (int idx = threadIdx.x; idx < 128 * 16; idx += 256) {
        const int r = idx >> 4, seg = idx & 15;
        size_t o = ((size_t)b * Nn + m0 + r) * Nn + n0 + seg * 8;
        *(uint4*)(g_sim_hi + o) = *(const uint4*)(sh + r * EPAD + seg * 8);
        *(uint4*)(g_sim_lo + o) = *(const uint4*)(sl + r * EPAD + seg * 8);
    }
    if (ti != tj) {
        for (int idx = threadIdx.x; idx < 128 * 16; idx += 256) {
            const int cc = idx >> 4, rseg = idx & 15;
            f16 th[8], tl[8];
            #pragma unroll
            for (int q = 0; q < 8; ++q) {
                th[q] = sh[(rseg * 8 + q) * EPAD + cc];
                tl[q] = sl[(rseg * 8 + q) * EPAD + cc];
            }
            size_t o = ((size_t)b * Nn + n0 + cc) * Nn + m0 + rseg * 8;
            *(uint4*)(g_sim_hi + o) = *(const uint4*)th;
            *(uint4*)(g_sim_lo + o) = *(const uint4*)tl;
        }
    }
}

// v = posenc @ sim (sim symmetric: B[n][k] = sim[n][k])
__global__ __launch_bounds__(256, 1) void k_mma_v() {
    const int b = blockIdx.z, m0 = blockIdx.y * 128, n0 = blockIdx.x * 128;
    float c[2][8][4] = {};
    mma_gemm(Nn / 64,
        [&](int kc, const f16** P, int* ld) {
            size_t a = (size_t)m0 * Dd + kc * 64;
            size_t o = ((size_t)b * Nn + n0) * Nn + kc * 64;
            P[0] = g_pe_hi + a; P[1] = g_pe_lo + a; P[2] = g_sim_hi + o;
            ld[0] = ld[1] = Dd; ld[2] = Nn;
        }, c);
    epi_loop(m0, n0, c, [&](int row, int col, float v0, float v1) {
        f16 h0, l0, h1, l1;
        split2(v0, h0, l0);
        split2(v1, h1, l1);
        size_t o = ((size_t)b * Nn + row) * Nn + col;
        *(__half2*)(g_v_hi + o) = __half2(h0, h1);
        *(__half2*)(g_v_lo + o) = __half2(l0, l1);
    });
}

// counter = softplus(v @ W_exp[1:] + csum*W_exp[0] + b_exp)
__global__ __launch_bounds__(256, 1) void k_mma_counter(const float* __restrict__ W_exp,
                                                        const float* __restrict__ b_exp) {
    const int b = blockIdx.z, m0 = blockIdx.y * 128, n0 = blockIdx.x * 128;
    float c[2][8][4] = {};
    mma_gemm(Nn / 64,
        [&](int kc, const f16** P, int* ld) {
            size_t a = ((size_t)b * Nn + m0) * Nn + kc * 64;
            size_t o = (size_t)n0 * Dd + kc * 64;
            P[0] = g_v_hi + a; P[1] = g_v_lo + a; P[2] = g_weT_hi + o;
            ld[0] = ld[1] = Nn; ld[2] = Dd;
        }, c);
    epi_loop(m0, n0, c, [&](int row, int col, float v0, float v1) {
        const float cs = g_csum[b * Nn + row];
        float x0 = v0 + cs * W_exp[col] + b_exp[col];
        float x1 = v1 + cs * W_exp[col + 1] + b_exp[col + 1];
        float s0 = fmaxf(x0, 0.f) + log1pf(expf(-fabsf(x0)));
        float s1 = fmaxf(x1, 0.f) + log1pf(expf(-fabsf(x1)));
        f16 h0, l0, h1, l1;
        split2(s0, h0, l0);
        split2(s1, h1, l1);
        size_t o = ((size_t)b * Nn + row) * Dd + col;
        *(__half2*)(g_ctr_hi + o) = __half2(h0, h1);
        *(__half2*)(g_ctr_lo + o) = __half2(l0, l1);
    });
}

// out = data @ W_merge[:D] + counter @ W_merge[D:], fp32
__global__ __launch_bounds__(256, 1) void k_mma_out(float* __restrict__ outp) {
    const int b = blockIdx.z, m0 = blockIdx.y * 128, n0 = blockIdx.x * 128;
    float c[2][8][4] = {};
    mma_gemm(2 * Dd / 64,
        [&](int kc, const f16** P, int* ld) {
            if (kc < Dd / 64) {
                size_t a = ((size_t)b * Nn + m0) * Dd + kc * 64;
                size_t o = (size_t)n0 * (2 * Dd) + kc * 64;
                P[0] = g_dat_hi + a; P[1] = g_dat_lo + a; P[2] = g_wmT_hi + o;
            } else {
                size_t a = ((size_t)b * Nn + m0) * Dd + (kc - Dd / 64) * 64;
                size_t o = (size_t)n0 * (2 * Dd) + Dd + (kc - Dd / 64) * 64;
                P[0] = g_ctr_hi + a; P[1] = g_ctr_lo + a; P[2] = g_wmT_hi + o;
            }
            ld[0] = ld[1] = Dd; ld[2] = 2 * Dd;
        }, c);
    epi_loop(m0, n0, c, [&](int row, int col, float v0, float v1) {
        size_t o = ((size_t)b * Nn + row) * Dd + col;
        float2 v; v.x = v0; v.y = v1;
        *(float2*)(outp + o) = v;
    });
}

// =================== prep / pointwise kernels ===================

__global__ __launch_bounds__(256) void k_prep_data(const float* __restrict__ data) {
    const int row = blockIdx.x;  // b*Nn + n
    const float* in = data + (size_t)row * Dd;
    float s = 0.f;
    for (int i = threadIdx.x; i < Dd; i += 256) { float v = in[i]; s += v * v; }
    __shared__ float red[32];
    #pragma unroll
    for (int o = 16; o; o >>= 1) s += __shfl_down_sync(0xffffffffu, s, o);
    if ((threadIdx.x & 31) == 0) red[threadIdx.x >> 5] = s;
    __syncthreads();
    if (threadIdx.x < 32) {
        float v = (threadIdx.x < 8) ? red[threadIdx.x] : 0.f;
        #pragma unroll
        for (int o = 4; o; o >>= 1) v += __shfl_down_sync(0xffffffffu, v, o);
        if (threadIdx.x == 0) red[0] = rsqrtf(fmaxf(v, 1e-12f));
    }
    __syncthreads();
    const float r = red[0];
    size_t base = (size_t)row * Dd;
    for (int i = threadIdx.x; i < Dd; i += 256) {
        float v = in[i];
        f16 h, l;
        split2(v, h, l);
        g_dat_hi[base + i] = h; g_dat_lo[base + i] = l;
        split2(v * r, h, l);
        g_cn_hi[base + i] = h; g_cn_lo[base + i] = l;
    }
}

__global__ __launch_bounds__(256) void k_prep_pe() {
    const int idx = blockIdx.x * 256 + threadIdx.x;
    const int n = idx / Dd;
    const int i = idx - n * Dd;
    const float e = (float)(2 * (i / 2)) / (float)Dd;
    const float rate = 1.0f / powf(10000.0f, e);
    const float ang = (float)n * rate;
    float v = (i & 1) ? cosf(ang) : sinf(ang);
    f16 h, l;
    split2(v, h, l);
    g_pe_hi[idx] = h; g_pe_lo[idx] = l;
}

// W_expT[n][k] = W_exp[(k+1)*Dd + n], hi only
__global__ void k_prep_weT(const float* __restrict__ W_exp) {
    __shared__ float t[32][33];
    const int x = blockIdx.x * 32 + threadIdx.x;  // n (src col)
    const int y = blockIdx.y * 32 + threadIdx.y;  // k (src row)
    t[threadIdx.y][threadIdx.x] = W_exp[(size_t)(y + 1) * Dd + x];
    __syncthreads();
    const int n = blockIdx.x * 32 + threadIdx.y;
    const int k = blockIdx.y * 32 + threadIdx.x;
    g_weT_hi[(size_t)n * Dd + k] = __float2half_rn(t[threadIdx.x][threadIdx.y]);
}

// W_mergeT[n][k] = W_merge[k*Dd + n], hi only
__global__ void k_prep_wmT(const float* __restrict__ W_merge) {
    __shared__ float t[32][33];
    const int x = blockIdx.x * 32 + threadIdx.x;  // n
    const int y = blockIdx.y * 32 + threadIdx.y;  // k
    t[threadIdx.y][threadIdx.x] = W_merge[(size_t)y * Dd + x];
    __syncthreads();
    const int n = blockIdx.x * 32 + threadIdx.y;
    const int k = blockIdx.y * 32 + threadIdx.x;
    g_wmT_hi[(size_t)n * (2 * Dd) + k] = __float2half_rn(t[threadIdx.x][threadIdx.y]);
}

__global__ __launch_bounds__(256) void k_rowsum() {
    const int row = blockIdx.x;  // b*Nn + n
    const f16* sh = g_sim_hi + (size_t)row * Nn;
    const f16* sl = g_sim_lo + (size_t)row * Nn;
    float acc = 0.f;
    for (int i = threadIdx.x; i < Nn; i += 256)
        acc += __half2float(sh[i]) + __half2float(sl[i]);
    __shared__ float red[32];
    #pragma unroll
    for (int o = 16; o; o >>= 1) acc += __shfl_down_sync(0xffffffffu, acc, o);
    if ((threadIdx.x & 31) == 0) red[threadIdx.x >> 5] = acc;
    __syncthreads();
    if (threadIdx.x < 32) {
        float v = (threadIdx.x < 8) ? red[threadIdx.x] : 0.f;
        #pragma unroll
        for (int o = 4; o; o >>= 1) v += __shfl_down_sync(0xffffffffu, v, o);
        if (threadIdx.x == 0) g_csum[row] = v;
    }
}

// =================== launch ===================

extern "C" void kernel_launch(void* const* d_in, const int* in_sizes, int n_in,
                              void* d_out, int out_size) {
    const float* data    = (const float*)d_in[0];
    const float* W_exp   = (const float*)d_in[1];
    const float* b_exp   = (const float*)d_in[2];
    const float* W_merge = (const float*)d_in[3];
    float* out = (float*)d_out;
    (void)in_sizes; (void)n_in; (void)out_size;

    cudaFuncSetAttribute(k_mma_sim,     cudaFuncAttributeMaxDynamicSharedMemorySize, SMEM_DYN);
    cudaFuncSetAttribute(k_mma_v,       cudaFuncAttributeMaxDynamicSharedMemorySize, SMEM_DYN);
    cudaFuncSetAttribute(k_mma_counter, cudaFuncAttributeMaxDynamicSharedMemorySize, SMEM_DYN);
    cudaFuncSetAttribute(k_mma_out,     cudaFuncAttributeMaxDynamicSharedMemorySize, SMEM_DYN);

    const dim3 tgrid(Nn / 128, Nn / 128, Bb);

    k_prep_data<<<Bb * Nn, 256>>>(data);
    k_prep_pe<<<(Nn * Dd) / 256, 256>>>();
    k_prep_weT<<<dim3(Dd / 32, Dd / 32), dim3(32, 32)>>>(W_exp);
    k_prep_wmT<<<dim3(Dd / 32, (2 * Dd) / 32), dim3(32, 32)>>>(W_merge);

    k_mma_sim<<<dim3(136, 1, Bb), 256, SMEM_DYN>>>();
    k_rowsum<<<Bb * Nn, 256>>>();
    k_mma_v<<<tgrid, 256, SMEM_DYN>>>();
    k_mma_counter<<<tgrid, 256, SMEM_DYN>>>(W_exp, b_exp);
    k_mma_out<<<tgrid, 256, SMEM_DYN>>>(out);
}

// round 7
// speedup vs baseline: 6.5889x; 1.2001x over previous
#include <cuda_runtime.h>
#include <cuda_fp16.h>
#include <math.h>
#include <stdint.h>

#define Bb 4
#define Nn 2048
#define Dd 2048
typedef __half f16;

// ---- scratch (static __device__; no allocations allowed) ----
__device__ f16 g_cn_hi[(size_t)Bb * Nn * Dd];
__device__ f16 g_cn_lo[(size_t)Bb * Nn * Dd];
__device__ f16 g_dat_hi[(size_t)Bb * Nn * Dd];
__device__ f16 g_dat_lo[(size_t)Bb * Nn * Dd];
__device__ f16 g_sim_hi[(size_t)Bb * Nn * Nn];
__device__ f16 g_sim_lo[(size_t)Bb * Nn * Nn];   // only rowsum reads lo
__device__ f16 g_pe_hi[(size_t)Nn * Dd];
__device__ f16 g_pe_lo[(size_t)Nn * Dd];
__device__ f16 g_v_hi[(size_t)Bb * Nn * Nn];
__device__ f16 g_v_lo[(size_t)Bb * Nn * Nn];
__device__ f16 g_ctr_hi[(size_t)Bb * Nn * Dd];
__device__ f16 g_ctr_lo[(size_t)Bb * Nn * Dd];
__device__ f16 g_weT_hi[(size_t)Dd * Dd];        // B-role only: hi only
__device__ f16 g_wmT_hi[(size_t)2 * Dd * Dd];    // B-role only: hi only
__device__ float g_csum[Bb * Nn];

// =================== helpers ===================

__device__ __forceinline__ void split2(float x, f16& h, f16& l) {
    h = __float2half_rn(x);
    l = __float2half_rn(x - __half2float(h));
}

__device__ __forceinline__ void cp16(uint32_t s, const void* g) {
    asm volatile("cp.async.cg.shared.global [%0], [%1], 16;" :: "r"(s), "l"(g));
}
__device__ __forceinline__ void cp_commit() {
    asm volatile("cp.async.commit_group;" ::: "memory");
}
__device__ __forceinline__ void cp_wait2() {
    asm volatile("cp.async.wait_group 2;" ::: "memory");
}

__device__ __forceinline__ void ldsm4(uint32_t& r0, uint32_t& r1, uint32_t& r2,
                                      uint32_t& r3, uint32_t a) {
    asm volatile("ldmatrix.sync.aligned.m8n8.x4.shared.b16 {%0,%1,%2,%3}, [%4];"
                 : "=r"(r0), "=r"(r1), "=r"(r2), "=r"(r3) : "r"(a));
}

__device__ __forceinline__ void mma_f16(float* c, const uint32_t* a, const uint32_t* b) {
    asm volatile("mma.sync.aligned.m16n8k16.row.col.f32.f16.f16.f32 "
                 "{%0,%1,%2,%3}, {%4,%5,%6,%7}, {%8,%9}, {%0,%1,%2,%3};"
                 : "+f"(c[0]), "+f"(c[1]), "+f"(c[2]), "+f"(c[3])
                 : "r"(a[0]), "r"(a[1]), "r"(a[2]), "r"(a[3]), "r"(b[0]), "r"(b[1]));
}

// =================== MMA GEMM core ===================
// CTA tile 128(m) x 128(n), K-chunk 32. 8 warps: 4(m) x 2(n) -> warp 32m x 64n.
// Tiles per stage: Ah, Al, Bh (128x32 fp16 = 8KB each) = 24KB; 4 stages = 96KB
// -> 2 CTAs/SM. 2-pass split accumulate: C += Ah*Bh + Al*Bh (fp32 acc).

#define TILE_B   8192
#define STAGE_B  (3 * TILE_B)
#define NSTAGE   4
#define SMEM_DYN (NSTAGE * STAGE_B)   // 98304

// swizzled smem offset within a 128x32-f16 tile (row stride 64B, 4x 16B cols)
__device__ __forceinline__ uint32_t swz(uint32_t row, uint32_t c16) {
    return row * 64u + ((c16 ^ ((row >> 1) & 3u)) << 4);
}

// srcf(kc, P[3], ld[3]): pointers for Ah, Al, Bh at this K-chunk (K-major)
template <typename SrcF>
__device__ __forceinline__ void mma_gemm(int KC, SrcF srcf, float c[2][8][4]) {
    extern __shared__ char smem[];
    const int tid = threadIdx.x;
    const int lane = tid & 31;
    const int wid = tid >> 5;
    const int wm = wid >> 1, wn = wid & 1;
    const uint32_t sbase = (uint32_t)__cvta_generic_to_shared(smem);

    auto load_stage = [&](int kc, int s) {
        const f16* P[3]; int ld[3];
        srcf(kc, P, ld);
        const int row = tid >> 1;
        const int c0 = (tid & 1) * 2;
        #pragma unroll
        for (int t = 0; t < 3; ++t) {
            const f16* src = P[t] + (size_t)row * ld[t] + c0 * 8;
            uint32_t dst = sbase + s * STAGE_B + t * TILE_B;
            cp16(dst + swz(row, c0),     src);
            cp16(dst + swz(row, c0 + 1), src + 8);
        }
    };

    auto compute = [&](int s) {
        const uint32_t base = sbase + s * STAGE_B;
        #pragma unroll
        for (int ks = 0; ks < 2; ++ks) {
            uint32_t ah[2][4], al[2][4], bh[8][2];
            #pragma unroll
            for (int mi = 0; mi < 2; ++mi) {
                uint32_t row = wm * 32 + mi * 16 + (lane & 15);
                uint32_t c16 = ks * 2 + (lane >> 4);
                uint32_t off = swz(row, c16);
                ldsm4(ah[mi][0], ah[mi][1], ah[mi][2], ah[mi][3], base + off);
                ldsm4(al[mi][0], al[mi][1], al[mi][2], al[mi][3], base + TILE_B + off);
            }
            #pragma unroll
            for (int j2 = 0; j2 < 4; ++j2) {
                uint32_t row = wn * 64 + j2 * 16 + ((lane >> 4) << 3) + (lane & 7);
                uint32_t c16 = ks * 2 + ((lane >> 3) & 1);
                uint32_t off = swz(row, c16);
                ldsm4(bh[2 * j2][0], bh[2 * j2][1], bh[2 * j2 + 1][0], bh[2 * j2 + 1][1],
                      base + 2 * TILE_B + off);
            }
            #pragma unroll
            for (int mi = 0; mi < 2; ++mi)
                #pragma unroll
                for (int nj = 0; nj < 8; ++nj)
                    mma_f16(c[mi][nj], ah[mi], bh[nj]);
            #pragma unroll
            for (int mi = 0; mi < 2; ++mi)
                #pragma unroll
                for (int nj = 0; nj < 8; ++nj)
                    mma_f16(c[mi][nj], al[mi], bh[nj]);
        }
    };

    // prefetch 3 stages
    #pragma unroll
    for (int p = 0; p < NSTAGE - 1; ++p) {
        if (p < KC) load_stage(p, p);
        cp_commit();
    }
    for (int kc = 0; kc < KC; ++kc) {
        cp_wait2();          // oldest outstanding group (stage kc) complete
        __syncthreads();     // all warps past compute of stage (kc-1)&3 before reload
        const int pf = kc + NSTAGE - 1;
        if (pf < KC) load_stage(pf, pf & (NSTAGE - 1));
        cp_commit();
        compute(kc & (NSTAGE - 1));
    }
    __syncthreads();         // smem safe for epilogue reuse
}

// epilogue iteration: calls body(row, col, v0, v1) for each accumulator pair
template <typename BodyF>
__device__ __forceinline__ void epi_loop(int m0, int n0, float c[2][8][4], BodyF body) {
    const int lane = threadIdx.x & 31;
    const int wid = threadIdx.x >> 5;
    const int wm = wid >> 1, wn = wid & 1;
    #pragma unroll
    for (int mi = 0; mi < 2; ++mi)
        #pragma unroll
        for (int nj = 0; nj < 8; ++nj)
            #pragma unroll
            for (int h = 0; h < 2; ++h) {
                const int row = m0 + wm * 32 + mi * 16 + (lane >> 2) + h * 8;
                const int col = n0 + wn * 64 + nj * 8 + (lane & 3) * 2;
                body(row, col, c[mi][nj][2 * h], c[mi][nj][2 * h + 1]);
            }
}

// =================== GEMM kernels ===================

// sim = relu(cn @ cn^T), split-stored, symmetric: only upper-tri tiles computed,
// mirrored through padded smem. grid.x = 136 (= 16*17/2)
#define EPAD 136
__global__ __launch_bounds__(256, 2) void k_mma_sim() {
    const int b = blockIdx.z;
    int t = blockIdx.x, ti = 0;
    while (t >= 16 - ti) { t -= 16 - ti; ++ti; }
    const int tj = ti + t;
    const int m0 = ti * 128, n0 = tj * 128;

    float c[2][8][4] = {};
    mma_gemm(Dd / 32,
        [&](int kc, const f16** P, int* ld) {
            size_t a = ((size_t)b * Nn + m0) * Dd + kc * 32;
            size_t o = ((size_t)b * Nn + n0) * Dd + kc * 32;
            P[0] = g_cn_hi + a; P[1] = g_cn_lo + a; P[2] = g_cn_hi + o;
            ld[0] = ld[1] = ld[2] = Dd;
        }, c);

    extern __shared__ char smem[];
    f16* sh = (f16*)smem;                       // [128][EPAD]
    f16* sl = (f16*)(smem + 128 * EPAD * 2);    // [128][EPAD]
    epi_loop(0, 0, c, [&](int r, int col, float v0, float v1) {
        f16 h0, l0, h1, l1;
        split2(fmaxf(v0, 0.f), h0, l0);
        split2(fmaxf(v1, 0.f), h1, l1);
        sh[r * EPAD + col] = h0; sh[r * EPAD + col + 1] = h1;
        sl[r * EPAD + col] = l0; sl[r * EPAD + col + 1] = l1;
    });
    __syncthreads();

    for (int idx = threadIdx.x; idx < 128 * 16; idx += 256) {
        const int r = idx >> 4, seg = idx & 15;
        size_t o = ((size_t)b * Nn + m0 + r) * Nn + n0 + seg * 8;
        *(uint4*)(g_sim_hi + o) = *(const uint4*)(sh + r * EPAD + seg * 8);
        *(uint4*)(g_sim_lo + o) = *(const uint4*)(sl + r * EPAD + seg * 8);
    }
    if (ti != tj) {
        for (int idx = threadIdx.x; idx < 128 * 16; idx += 256) {
            const int cc = idx >> 4, rseg = idx & 15;
            f16 th[8], tl[8];
            #pragma unroll
            for (int q = 0; q < 8; ++q) {
                th[q] = sh[(rseg * 8 + q) * EPAD + cc];
                tl[q] = sl[(rseg * 8 + q) * EPAD + cc];
            }
            size_t o = ((size_t)b * Nn + n0 + cc) * Nn + m0 + rseg * 8;
            *(uint4*)(g_sim_hi + o) = *(const uint4*)th;
            *(uint4*)(g_sim_lo + o) = *(const uint4*)tl;
        }
    }
}

// v = posenc @ sim (sim symmetric: B[n][k] = sim[n][k])
__global__ __launch_bounds__(256, 2) void k_mma_v() {
    const int b = blockIdx.z, m0 = blockIdx.y * 128, n0 = blockIdx.x * 128;
    float c[2][8][4] = {};
    mma_gemm(Nn / 32,
        [&](int kc, const f16** P, int* ld) {
            size_t a = (size_t)m0 * Dd + kc * 32;
            size_t o = ((size_t)b * Nn + n0) * Nn + kc * 32;
            P[0] = g_pe_hi + a; P[1] = g_pe_lo + a; P[2] = g_sim_hi + o;
            ld[0] = ld[1] = Dd; ld[2] = Nn;
        }, c);
    epi_loop(m0, n0, c, [&](int row, int col, float v0, float v1) {
        f16 h0, l0, h1, l1;
        split2(v0, h0, l0);
        split2(v1, h1, l1);
        size_t o = ((size_t)b * Nn + row) * Nn + col;
        *(__half2*)(g_v_hi + o) = __half2(h0, h1);
        *(__half2*)(g_v_lo + o) = __half2(l0, l1);
    });
}

// counter = softplus(v @ W_exp[1:] + csum*W_exp[0] + b_exp)
__global__ __launch_bounds__(256, 2) void k_mma_counter(const float* __restrict__ W_exp,
                                                        const float* __restrict__ b_exp) {
    const int b = blockIdx.z, m0 = blockIdx.y * 128, n0 = blockIdx.x * 128;
    float c[2][8][4] = {};
    mma_gemm(Nn / 32,
        [&](int kc, const f16** P, int* ld) {
            size_t a = ((size_t)b * Nn + m0) * Nn + kc * 32;
            size_t o = (size_t)n0 * Dd + kc * 32;
            P[0] = g_v_hi + a; P[1] = g_v_lo + a; P[2] = g_weT_hi + o;
            ld[0] = ld[1] = Nn; ld[2] = Dd;
        }, c);
    epi_loop(m0, n0, c, [&](int row, int col, float v0, float v1) {
        const float cs = g_csum[b * Nn + row];
        float x0 = v0 + cs * W_exp[col] + b_exp[col];
        float x1 = v1 + cs * W_exp[col + 1] + b_exp[col + 1];
        float s0 = fmaxf(x0, 0.f) + log1pf(expf(-fabsf(x0)));
        float s1 = fmaxf(x1, 0.f) + log1pf(expf(-fabsf(x1)));
        f16 h0, l0, h1, l1;
        split2(s0, h0, l0);
        split2(s1, h1, l1);
        size_t o = ((size_t)b * Nn + row) * Dd + col;
        *(__half2*)(g_ctr_hi + o) = __half2(h0, h1);
        *(__half2*)(g_ctr_lo + o) = __half2(l0, l1);
    });
}

// out = data @ W_merge[:D] + counter @ W_merge[D:], fp32
__global__ __launch_bounds__(256, 2) void k_mma_out(float* __restrict__ outp) {
    const int b = blockIdx.z, m0 = blockIdx.y * 128, n0 = blockIdx.x * 128;
    float c[2][8][4] = {};
    mma_gemm(2 * Dd / 32,
        [&](int kc, const f16** P, int* ld) {
            if (kc < Dd / 32) {
                size_t a = ((size_t)b * Nn + m0) * Dd + kc * 32;
                size_t o = (size_t)n0 * (2 * Dd) + kc * 32;
                P[0] = g_dat_hi + a; P[1] = g_dat_lo + a; P[2] = g_wmT_hi + o;
            } else {
                size_t a = ((size_t)b * Nn + m0) * Dd + (kc - Dd / 32) * 32;
                size_t o = (size_t)n0 * (2 * Dd) + Dd + (kc - Dd / 32) * 32;
                P[0] = g_ctr_hi + a; P[1] = g_ctr_lo + a; P[2] = g_wmT_hi + o;
            }
            ld[0] = ld[1] = Dd; ld[2] = 2 * Dd;
        }, c);
    epi_loop(m0, n0, c, [&](int row, int col, float v0, float v1) {
        size_t o = ((size_t)b * Nn + row) * Dd + col;
        float2 v; v.x = v0; v.y = v1;
        *(float2*)(outp + o) = v;
    });
}

// =================== prep / pointwise kernels ===================

__global__ __launch_bounds__(256) void k_prep_data(const float* __restrict__ data) {
    const int row = blockIdx.x;  // b*Nn + n
    const float* in = data + (size_t)row * Dd;
    float s = 0.f;
    for (int i = threadIdx.x; i < Dd; i += 256) { float v = in[i]; s += v * v; }
    __shared__ float red[32];
    #pragma unroll
    for (int o = 16; o; o >>= 1) s += __shfl_down_sync(0xffffffffu, s, o);
    if ((threadIdx.x & 31) == 0) red[threadIdx.x >> 5] = s;
    __syncthreads();
    if (threadIdx.x < 32) {
        float v = (threadIdx.x < 8) ? red[threadIdx.x] : 0.f;
        #pragma unroll
        for (int o = 4; o; o >>= 1) v += __shfl_down_sync(0xffffffffu, v, o);
        if (threadIdx.x == 0) red[0] = rsqrtf(fmaxf(v, 1e-12f));
    }
    __syncthreads();
    const float r = red[0];
    size_t base = (size_t)row * Dd;
    for (int i = threadIdx.x; i < Dd; i += 256) {
        float v = in[i];
        f16 h, l;
        split2(v, h, l);
        g_dat_hi[base + i] = h; g_dat_lo[base + i] = l;
        split2(v * r, h, l);
        g_cn_hi[base + i] = h; g_cn_lo[base + i] = l;
    }
}

__global__ __launch_bounds__(256) void k_prep_pe() {
    const int idx = blockIdx.x * 256 + threadIdx.x;
    const int n = idx / Dd;
    const int i = idx - n * Dd;
    const float e = (float)(2 * (i / 2)) / (float)Dd;
    const float rate = 1.0f / powf(10000.0f, e);
    const float ang = (float)n * rate;
    float v = (i & 1) ? cosf(ang) : sinf(ang);
    f16 h, l;
    split2(v, h, l);
    g_pe_hi[idx] = h; g_pe_lo[idx] = l;
}

// W_expT[n][k] = W_exp[(k+1)*Dd + n], hi only
__global__ void k_prep_weT(const float* __restrict__ W_exp) {
    __shared__ float t[32][33];
    const int x = blockIdx.x * 32 + threadIdx.x;  // n (src col)
    const int y = blockIdx.y * 32 + threadIdx.y;  // k (src row)
    t[threadIdx.y][threadIdx.x] = W_exp[(size_t)(y + 1) * Dd + x];
    __syncthreads();
    const int n = blockIdx.x * 32 + threadIdx.y;
    const int k = blockIdx.y * 32 + threadIdx.x;
    g_weT_hi[(size_t)n * Dd + k] = __float2half_rn(t[threadIdx.x][threadIdx.y]);
}

// W_mergeT[n][k] = W_merge[k*Dd + n], hi only
__global__ void k_prep_wmT(const float* __restrict__ W_merge) {
    __shared__ float t[32][33];
    const int x = blockIdx.x * 32 + threadIdx.x;  // n
    const int y = blockIdx.y * 32 + threadIdx.y;  // k
    t[threadIdx.y][threadIdx.x] = W_merge[(size_t)y * Dd + x];
    __syncthreads();
    const int n = blockIdx.x * 32 + threadIdx.y;
    const int k = blockIdx.y * 32 + threadIdx.x;
    g_wmT_hi[(size_t)n * (2 * Dd) + k] = __float2half_rn(t[threadIdx.x][threadIdx.y]);
}

__global__ __launch_bounds__(256) void k_rowsum() {
    const int row = blockIdx.x;  // b*Nn + n
    const f16* sh = g_sim_hi + (size_t)row * Nn;
    const f16* sl = g_sim_lo + (size_t)row * Nn;
    float acc = 0.f;
    for (int i = threadIdx.x; i < Nn; i += 256)
        acc += __half2float(sh[i]) + __half2float(sl[i]);
    __shared__ float red[32];
    #pragma unroll
    for (int o = 16; o; o >>= 1) acc += __shfl_down_sync(0xffffffffu, acc, o);
    if ((threadIdx.x & 31) == 0) red[threadIdx.x >> 5] = acc;
    __syncthreads();
    if (threadIdx.x < 32) {
        float v = (threadIdx.x < 8) ? red[threadIdx.x] : 0.f;
        #pragma unroll
        for (int o = 4; o; o >>= 1) v += __shfl_down_sync(0xffffffffu, v, o);
        if (threadIdx.x == 0) g_csum[row] = v;
    }
}

// =================== launch ===================

extern "C" void kernel_launch(void* const* d_in, const int* in_sizes, int n_in,
                              void* d_out, int out_size) {
    const float* data    = (const float*)d_in[0];
    const float* W_exp   = (const float*)d_in[1];
    const float* b_exp   = (const float*)d_in[2];
    const float* W_merge = (const float*)d_in[3];
    float* out = (float*)d_out;
    (void)in_sizes; (void)n_in; (void)out_size;

    cudaFuncSetAttribute(k_mma_sim,     cudaFuncAttributeMaxDynamicSharedMemorySize, SMEM_DYN);
    cudaFuncSetAttribute(k_mma_v,       cudaFuncAttributeMaxDynamicSharedMemorySize, SMEM_DYN);
    cudaFuncSetAttribute(k_mma_counter, cudaFuncAttributeMaxDynamicSharedMemorySize, SMEM_DYN);
    cudaFuncSetAttribute(k_mma_out,     cudaFuncAttributeMaxDynamicSharedMemorySize, SMEM_DYN);

    const dim3 tgrid(Nn / 128, Nn / 128, Bb);

    k_prep_data<<<Bb * Nn, 256>>>(data);
    k_prep_pe<<<(Nn * Dd) / 256, 256>>>();
    k_prep_weT<<<dim3(Dd / 32, Dd / 32), dim3(32, 32)>>>(W_exp);
    k_prep_wmT<<<dim3(Dd / 32, (2 * Dd) / 32), dim3(32, 32)>>>(W_merge);

    k_mma_sim<<<dim3(136, 1, Bb), 256, SMEM_DYN>>>();
    k_rowsum<<<Bb * Nn, 256>>>();
    k_mma_v<<<tgrid, 256, SMEM_DYN>>>();
    k_mma_counter<<<tgrid, 256, SMEM_DYN>>>(W_exp, b_exp);
    k_mma_out<<<tgrid, 256, SMEM_DYN>>>(out);
}

// round 8
// speedup vs baseline: 10.2700x; 1.5587x over previous
#include <cuda_runtime.h>
#include <cuda_fp16.h>
#include <math.h>
#include <stdint.h>

#define Bb 4
#define Nn 2048
#define Dd 2048
typedef __half f16;

// ---- scratch (static __device__; no allocations allowed) ----
__device__ f16 g_cn_hi[(size_t)Bb * Nn * Dd];
__device__ f16 g_cn_lo[(size_t)Bb * Nn * Dd];   // sim stays 2-pass
__device__ f16 g_dat_hi[(size_t)Bb * Nn * Dd];
__device__ f16 g_sim_hi[(size_t)Bb * Nn * Nn];
__device__ f16 g_pe_hi[(size_t)Nn * Dd];
__device__ f16 g_v_hi[(size_t)Bb * Nn * Nn];
__device__ f16 g_ctr_hi[(size_t)Bb * Nn * Dd];
__device__ f16 g_weT_hi[(size_t)Dd * Dd];
__device__ f16 g_wmT_hi[(size_t)2 * Dd * Dd];
__device__ float g_csum[Bb * Nn];

// =================== helpers ===================

__device__ __forceinline__ void split2(float x, f16& h, f16& l) {
    h = __float2half_rn(x);
    l = __float2half_rn(x - __half2float(h));
}

__device__ __forceinline__ void cp16(uint32_t s, const void* g) {
    asm volatile("cp.async.cg.shared.global [%0], [%1], 16;" :: "r"(s), "l"(g));
}
__device__ __forceinline__ void cp_commit() {
    asm volatile("cp.async.commit_group;" ::: "memory");
}
__device__ __forceinline__ void cp_wait2() {
    asm volatile("cp.async.wait_group 2;" ::: "memory");
}

__device__ __forceinline__ void ldsm4(uint32_t& r0, uint32_t& r1, uint32_t& r2,
                                      uint32_t& r3, uint32_t a) {
    asm volatile("ldmatrix.sync.aligned.m8n8.x4.shared.b16 {%0,%1,%2,%3}, [%4];"
                 : "=r"(r0), "=r"(r1), "=r"(r2), "=r"(r3) : "r"(a));
}

__device__ __forceinline__ void mma_f16(float* c, const uint32_t* a, const uint32_t* b) {
    asm volatile("mma.sync.aligned.m16n8k16.row.col.f32.f16.f16.f32 "
                 "{%0,%1,%2,%3}, {%4,%5,%6,%7}, {%8,%9}, {%0,%1,%2,%3};"
                 : "+f"(c[0]), "+f"(c[1]), "+f"(c[2]), "+f"(c[3])
                 : "r"(a[0]), "r"(a[1]), "r"(a[2]), "r"(a[3]), "r"(b[0]), "r"(b[1]));
}

// =================== MMA GEMM core ===================
// CTA tile 128(m) x 128(n), K-chunk 32. 8 warps: 4(m) x 2(n) -> warp 32m x 64n.
// NA = number of A passes (1 or 2). Tiles per stage: NA x A + 1 x B (8KB each).
// 4 stages. NA=1: 64KB smem; NA=2: 96KB. Both -> 2 CTAs/SM.

#define TILE_B   8192
#define NSTAGE   4

// swizzled smem offset within a 128x32-f16 tile (row stride 64B, 4x 16B cols)
__device__ __forceinline__ uint32_t swz(uint32_t row, uint32_t c16) {
    return row * 64u + ((c16 ^ ((row >> 1) & 3u)) << 4);
}

// srcf(kc, P[NA+1], ld[NA+1]): K-major pointers, A tiles first, then B
template <int NA, typename SrcF>
__device__ __forceinline__ void mma_gemm(int KC, SrcF srcf, float c[2][8][4]) {
    constexpr int NT = NA + 1;
    constexpr int STAGE_B = NT * TILE_B;
    extern __shared__ char smem[];
    const int tid = threadIdx.x;
    const int lane = tid & 31;
    const int wid = tid >> 5;
    const int wm = wid >> 1, wn = wid & 1;
    const uint32_t sbase = (uint32_t)__cvta_generic_to_shared(smem);

    auto load_stage = [&](int kc, int s) {
        const f16* P[NT]; int ld[NT];
        srcf(kc, P, ld);
        const int row = tid >> 1;
        const int c0 = (tid & 1) * 2;
        #pragma unroll
        for (int t = 0; t < NT; ++t) {
            const f16* src = P[t] + (size_t)row * ld[t] + c0 * 8;
            uint32_t dst = sbase + s * STAGE_B + t * TILE_B;
            cp16(dst + swz(row, c0),     src);
            cp16(dst + swz(row, c0 + 1), src + 8);
        }
    };

    auto compute = [&](int s) {
        const uint32_t base = sbase + s * STAGE_B;
        #pragma unroll
        for (int ks = 0; ks < 2; ++ks) {
            uint32_t a[NA][2][4], bh[8][2];
            #pragma unroll
            for (int na = 0; na < NA; ++na)
                #pragma unroll
                for (int mi = 0; mi < 2; ++mi) {
                    uint32_t row = wm * 32 + mi * 16 + (lane & 15);
                    uint32_t c16 = ks * 2 + (lane >> 4);
                    uint32_t off = swz(row, c16);
                    ldsm4(a[na][mi][0], a[na][mi][1], a[na][mi][2], a[na][mi][3],
                          base + na * TILE_B + off);
                }
            #pragma unroll
            for (int j2 = 0; j2 < 4; ++j2) {
                uint32_t row = wn * 64 + j2 * 16 + ((lane >> 4) << 3) + (lane & 7);
                uint32_t c16 = ks * 2 + ((lane >> 3) & 1);
                uint32_t off = swz(row, c16);
                ldsm4(bh[2 * j2][0], bh[2 * j2][1], bh[2 * j2 + 1][0], bh[2 * j2 + 1][1],
                      base + NA * TILE_B + off);
            }
            #pragma unroll
            for (int na = 0; na < NA; ++na)
                #pragma unroll
                for (int mi = 0; mi < 2; ++mi)
                    #pragma unroll
                    for (int nj = 0; nj < 8; ++nj)
                        mma_f16(c[mi][nj], a[na][mi], bh[nj]);
        }
    };

    // prefetch 3 stages
    #pragma unroll
    for (int p = 0; p < NSTAGE - 1; ++p) {
        if (p < KC) load_stage(p, p);
        cp_commit();
    }
    for (int kc = 0; kc < KC; ++kc) {
        cp_wait2();          // oldest outstanding group (stage kc) complete
        __syncthreads();     // all warps past compute of stage (kc-1)&3 before reload
        const int pf = kc + NSTAGE - 1;
        if (pf < KC) load_stage(pf, pf & (NSTAGE - 1));
        cp_commit();
        compute(kc & (NSTAGE - 1));
    }
    __syncthreads();         // smem safe for epilogue reuse
}

// epilogue iteration: calls body(row, col, v0, v1) for each accumulator pair
template <typename BodyF>
__device__ __forceinline__ void epi_loop(int m0, int n0, float c[2][8][4], BodyF body) {
    const int lane = threadIdx.x & 31;
    const int wid = threadIdx.x >> 5;
    const int wm = wid >> 1, wn = wid & 1;
    #pragma unroll
    for (int mi = 0; mi < 2; ++mi)
        #pragma unroll
        for (int nj = 0; nj < 8; ++nj)
            #pragma unroll
            for (int h = 0; h < 2; ++h) {
                const int row = m0 + wm * 32 + mi * 16 + (lane >> 2) + h * 8;
                const int col = n0 + wn * 64 + nj * 8 + (lane & 3) * 2;
                body(row, col, c[mi][nj][2 * h], c[mi][nj][2 * h + 1]);
            }
}

// =================== GEMM kernels ===================

// sim = relu(cn @ cn^T), 2-pass, symmetric: upper-tri tiles only, mirrored
// through padded smem. grid.x = 136 (= 16*17/2)
#define EPAD 136
#define SMEM_SIM (NSTAGE * 3 * TILE_B)   // 98304
#define SMEM_1P  (NSTAGE * 2 * TILE_B)   // 65536
__global__ __launch_bounds__(256, 2) void k_mma_sim() {
    const int b = blockIdx.z;
    int t = blockIdx.x, ti = 0;
    while (t >= 16 - ti) { t -= 16 - ti; ++ti; }
    const int tj = ti + t;
    const int m0 = ti * 128, n0 = tj * 128;

    float c[2][8][4] = {};
    mma_gemm<2>(Dd / 32,
        [&](int kc, const f16** P, int* ld) {
            size_t a = ((size_t)b * Nn + m0) * Dd + kc * 32;
            size_t o = ((size_t)b * Nn + n0) * Dd + kc * 32;
            P[0] = g_cn_hi + a; P[1] = g_cn_lo + a; P[2] = g_cn_hi + o;
            ld[0] = ld[1] = ld[2] = Dd;
        }, c);

    extern __shared__ char smem[];
    f16* sh = (f16*)smem;   // [128][EPAD]
    epi_loop(0, 0, c, [&](int r, int col, float v0, float v1) {
        sh[r * EPAD + col]     = __float2half_rn(fmaxf(v0, 0.f));
        sh[r * EPAD + col + 1] = __float2half_rn(fmaxf(v1, 0.f));
    });
    __syncthreads();

    for (int idx = threadIdx.x; idx < 128 * 16; idx += 256) {
        const int r = idx >> 4, seg = idx & 15;
        size_t o = ((size_t)b * Nn + m0 + r) * Nn + n0 + seg * 8;
        *(uint4*)(g_sim_hi + o) = *(const uint4*)(sh + r * EPAD + seg * 8);
    }
    if (ti != tj) {
        for (int idx = threadIdx.x; idx < 128 * 16; idx += 256) {
            const int cc = idx >> 4, rseg = idx & 15;
            f16 th[8];
            #pragma unroll
            for (int q = 0; q < 8; ++q)
                th[q] = sh[(rseg * 8 + q) * EPAD + cc];
            size_t o = ((size_t)b * Nn + n0 + cc) * Nn + m0 + rseg * 8;
            *(uint4*)(g_sim_hi + o) = *(const uint4*)th;
        }
    }
}

// v = posenc @ sim, 1-pass (sim symmetric: B[n][k] = sim[n][k])
__global__ __launch_bounds__(256, 2) void k_mma_v() {
    const int b = blockIdx.z, m0 = blockIdx.y * 128, n0 = blockIdx.x * 128;
    float c[2][8][4] = {};
    mma_gemm<1>(Nn / 32,
        [&](int kc, const f16** P, int* ld) {
            size_t a = (size_t)m0 * Dd + kc * 32;
            size_t o = ((size_t)b * Nn + n0) * Nn + kc * 32;
            P[0] = g_pe_hi + a; P[1] = g_sim_hi + o;
            ld[0] = Dd; ld[1] = Nn;
        }, c);
    epi_loop(m0, n0, c, [&](int row, int col, float v0, float v1) {
        size_t o = ((size_t)b * Nn + row) * Nn + col;
        *(__half2*)(g_v_hi + o) = __half2(__float2half_rn(v0), __float2half_rn(v1));
    });
}

// counter = softplus(v @ W_exp[1:] + csum*W_exp[0] + b_exp), 1-pass
__global__ __launch_bounds__(256, 2) void k_mma_counter(const float* __restrict__ W_exp,
                                                        const float* __restrict__ b_exp) {
    const int b = blockIdx.z, m0 = blockIdx.y * 128, n0 = blockIdx.x * 128;
    float c[2][8][4] = {};
    mma_gemm<1>(Nn / 32,
        [&](int kc, const f16** P, int* ld) {
            size_t a = ((size_t)b * Nn + m0) * Nn + kc * 32;
            size_t o = (size_t)n0 * Dd + kc * 32;
            P[0] = g_v_hi + a; P[1] = g_weT_hi + o;
            ld[0] = Nn; ld[1] = Dd;
        }, c);
    epi_loop(m0, n0, c, [&](int row, int col, float v0, float v1) {
        const float cs = g_csum[b * Nn + row];
        float x0 = v0 + cs * W_exp[col] + b_exp[col];
        float x1 = v1 + cs * W_exp[col + 1] + b_exp[col + 1];
        float s0 = fmaxf(x0, 0.f) + log1pf(expf(-fabsf(x0)));
        float s1 = fmaxf(x1, 0.f) + log1pf(expf(-fabsf(x1)));
        size_t o = ((size_t)b * Nn + row) * Dd + col;
        *(__half2*)(g_ctr_hi + o) = __half2(__float2half_rn(s0), __float2half_rn(s1));
    });
}

// out = data @ W_merge[:D] + counter @ W_merge[D:], 1-pass, fp32 out
__global__ __launch_bounds__(256, 2) void k_mma_out(float* __restrict__ outp) {
    const int b = blockIdx.z, m0 = blockIdx.y * 128, n0 = blockIdx.x * 128;
    float c[2][8][4] = {};
    mma_gemm<1>(2 * Dd / 32,
        [&](int kc, const f16** P, int* ld) {
            if (kc < Dd / 32) {
                size_t a = ((size_t)b * Nn + m0) * Dd + kc * 32;
                size_t o = (size_t)n0 * (2 * Dd) + kc * 32;
                P[0] = g_dat_hi + a; P[1] = g_wmT_hi + o;
            } else {
                size_t a = ((size_t)b * Nn + m0) * Dd + (kc - Dd / 32) * 32;
                size_t o = (size_t)n0 * (2 * Dd) + Dd + (kc - Dd / 32) * 32;
                P[0] = g_ctr_hi + a; P[1] = g_wmT_hi + o;
            }
            ld[0] = Dd; ld[1] = 2 * Dd;
        }, c);
    epi_loop(m0, n0, c, [&](int row, int col, float v0, float v1) {
        size_t o = ((size_t)b * Nn + row) * Dd + col;
        float2 v; v.x = v0; v.y = v1;
        *(float2*)(outp + o) = v;
    });
}

// =================== prep / pointwise kernels ===================

__global__ __launch_bounds__(256) void k_prep_data(const float* __restrict__ data) {
    const int row = blockIdx.x;  // b*Nn + n
    const float* in = data + (size_t)row * Dd;
    float s = 0.f;
    for (int i = threadIdx.x; i < Dd; i += 256) { float v = in[i]; s += v * v; }
    __shared__ float red[32];
    #pragma unroll
    for (int o = 16; o; o >>= 1) s += __shfl_down_sync(0xffffffffu, s, o);
    if ((threadIdx.x & 31) == 0) red[threadIdx.x >> 5] = s;
    __syncthreads();
    if (threadIdx.x < 32) {
        float v = (threadIdx.x < 8) ? red[threadIdx.x] : 0.f;
        #pragma unroll
        for (int o = 4; o; o >>= 1) v += __shfl_down_sync(0xffffffffu, v, o);
        if (threadIdx.x == 0) red[0] = rsqrtf(fmaxf(v, 1e-12f));
    }
    __syncthreads();
    const float r = red[0];
    size_t base = (size_t)row * Dd;
    for (int i = threadIdx.x; i < Dd; i += 256) {
        float v = in[i];
        g_dat_hi[base + i] = __float2half_rn(v);
        f16 h, l;
        split2(v * r, h, l);
        g_cn_hi[base + i] = h; g_cn_lo[base + i] = l;
    }
}

__global__ __launch_bounds__(256) void k_prep_pe() {
    const int idx = blockIdx.x * 256 + threadIdx.x;
    const int n = idx / Dd;
    const int i = idx - n * Dd;
    const float e = (float)(2 * (i / 2)) / (float)Dd;
    const float rate = 1.0f / powf(10000.0f, e);
    const float ang = (float)n * rate;
    float v = (i & 1) ? cosf(ang) : sinf(ang);
    g_pe_hi[idx] = __float2half_rn(v);
}

// W_expT[n][k] = W_exp[(k+1)*Dd + n], hi only
__global__ void k_prep_weT(const float* __restrict__ W_exp) {
    __shared__ float t[32][33];
    const int x = blockIdx.x * 32 + threadIdx.x;  // n (src col)
    const int y = blockIdx.y * 32 + threadIdx.y;  // k (src row)
    t[threadIdx.y][threadIdx.x] = W_exp[(size_t)(y + 1) * Dd + x];
    __syncthreads();
    const int n = blockIdx.x * 32 + threadIdx.y;
    const int k = blockIdx.y * 32 + threadIdx.x;
    g_weT_hi[(size_t)n * Dd + k] = __float2half_rn(t[threadIdx.x][threadIdx.y]);
}

// W_mergeT[n][k] = W_merge[k*Dd + n], hi only
__global__ void k_prep_wmT(const float* __restrict__ W_merge) {
    __shared__ float t[32][33];
    const int x = blockIdx.x * 32 + threadIdx.x;  // n
    const int y = blockIdx.y * 32 + threadIdx.y;  // k
    t[threadIdx.y][threadIdx.x] = W_merge[(size_t)y * Dd + x];
    __syncthreads();
    const int n = blockIdx.x * 32 + threadIdx.y;
    const int k = blockIdx.y * 32 + threadIdx.x;
    g_wmT_hi[(size_t)n * (2 * Dd) + k] = __float2half_rn(t[threadIdx.x][threadIdx.y]);
}

__global__ __launch_bounds__(256) void k_rowsum() {
    const int row = blockIdx.x;  // b*Nn + n
    const f16* sh = g_sim_hi + (size_t)row * Nn;
    float acc = 0.f;
    for (int i = threadIdx.x; i < Nn; i += 256)
        acc += __half2float(sh[i]);
    __shared__ float red[32];
    #pragma unroll
    for (int o = 16; o; o >>= 1) acc += __shfl_down_sync(0xffffffffu, acc, o);
    if ((threadIdx.x & 31) == 0) red[threadIdx.x >> 5] = acc;
    __syncthreads();
    if (threadIdx.x < 32) {
        float v = (threadIdx.x < 8) ? red[threadIdx.x] : 0.f;
        #pragma unroll
        for (int o = 4; o; o >>= 1) v += __shfl_down_sync(0xffffffffu, v, o);
        if (threadIdx.x == 0) g_csum[row] = v;
    }
}

// =================== launch ===================

extern "C" void kernel_launch(void* const* d_in, const int* in_sizes, int n_in,
                              void* d_out, int out_size) {
    const float* data    = (const float*)d_in[0];
    const float* W_exp   = (const float*)d_in[1];
    const float* b_exp   = (const float*)d_in[2];
    const float* W_merge = (const float*)d_in[3];
    float* out = (float*)d_out;
    (void)in_sizes; (void)n_in; (void)out_size;

    cudaFuncSetAttribute(k_mma_sim,     cudaFuncAttributeMaxDynamicSharedMemorySize, SMEM_SIM);
    cudaFuncSetAttribute(k_mma_v,       cudaFuncAttributeMaxDynamicSharedMemorySize, SMEM_1P);
    cudaFuncSetAttribute(k_mma_counter, cudaFuncAttributeMaxDynamicSharedMemorySize, SMEM_1P);
    cudaFuncSetAttribute(k_mma_out,     cudaFuncAttributeMaxDynamicSharedMemorySize, SMEM_1P);

    const dim3 tgrid(Nn / 128, Nn / 128, Bb);

    k_prep_data<<<Bb * Nn, 256>>>(data);
    k_prep_pe<<<(Nn * Dd) / 256, 256>>>();
    k_prep_weT<<<dim3(Dd / 32, Dd / 32), dim3(32, 32)>>>(W_exp);
    k_prep_wmT<<<dim3(Dd / 32, (2 * Dd) / 32), dim3(32, 32)>>>(W_merge);

    k_mma_sim<<<dim3(136, 1, Bb), 256, SMEM_SIM>>>();
    k_rowsum<<<Bb * Nn, 256>>>();
    k_mma_v<<<tgrid, 256, SMEM_1P>>>();
    k_mma_counter<<<tgrid, 256, SMEM_1P>>>(W_exp, b_exp);
    k_mma_out<<<tgrid, 256, SMEM_1P>>>(out);
}